// round 12
// baseline (speedup 1.0000x reference)
#include <cuda_runtime.h>
#include <cuda_bf16.h>
#include <cooperative_groups.h>
#include <cstdint>

namespace cg = cooperative_groups;

// Problem constants
#define BB 128          // batch
#define SS 1024         // seq
#define II 768          // input dim
#define HH 256          // hidden
#define OO 6            // output
#define MM (BB * SS)    // 131072 rows
#define G3 (3 * HH)     // 768 gate rows

#define KP   2304       // packed K' = 3*768 (bf16 hi|hi|lo)
#define KPB  (KP * 2)   // 4608 bytes per packed row
#define NCHUNK (KP / 64)    // 36
#define NSTG 3
#define STG_BYTES 49152     // A 16KB + B 32KB

typedef unsigned long long ull;

// ---------------------------------------------------------------------------
// Scratch (device globals — allocation-free rule)
// ---------------------------------------------------------------------------
__device__ __align__(128) float g_xg[(size_t)MM * G3];           // [M, 768]
__device__ __align__(128) float g_hs[(size_t)MM * HH];           // [M, 256]
__device__ __align__(128) __nv_bfloat16 g_ax[(size_t)MM * KP];   // packed A'
__device__ __align__(128) __nv_bfloat16 g_bx[(size_t)G3 * KP];   // packed B'

// ---------------------------------------------------------------------------
// Generic-PTX helpers
// ---------------------------------------------------------------------------
__device__ __forceinline__ uint32_t smem_u32(const void* p) {
    uint32_t r;
    asm("{ .reg .u64 t; cvta.to.shared.u64 t, %1; cvt.u32.u64 %0, t; }"
        : "=r"(r) : "l"(p));
    return r;
}

__device__ __forceinline__ void cpa16(uint32_t saddr, const char* g) {
    asm volatile("cp.async.cg.shared.global [%0], [%1], 16;" :: "r"(saddr), "l"(g));
}

#define LDSM_X4(r, addr) \
    asm volatile("ldmatrix.sync.aligned.m8n8.x4.shared.b16 {%0,%1,%2,%3}, [%4];" \
                 : "=r"((r)[0]), "=r"((r)[1]), "=r"((r)[2]), "=r"((r)[3]) : "r"(addr))

#define MMA_16816(d, a, b0, b1) \
    asm volatile("mma.sync.aligned.m16n8k16.row.col.f32.bf16.bf16.f32 " \
                 "{%0,%1,%2,%3}, {%4,%5,%6,%7}, {%8,%9}, {%0,%1,%2,%3};" \
                 : "+f"((d)[0]), "+f"((d)[1]), "+f"((d)[2]), "+f"((d)[3]) \
                 : "r"((a)[0]), "r"((a)[1]), "r"((a)[2]), "r"((a)[3]), \
                   "r"(b0), "r"(b1))

#define FMA2(acc, a, b) \
    asm("fma.rn.f32x2 %0, %1, %2, %0;" : "+l"(acc) : "l"(a), "l"(b))

#define MBAR_INIT(addr, cnt) \
    asm volatile("mbarrier.init.shared.b64 [%0], %1;" :: "r"(addr), "r"(cnt) : "memory")

#define MBAR_EXPECT_TX(addr, tx) \
    asm volatile("mbarrier.arrive.expect_tx.shared.b64 _, [%0], %1;" \
                 :: "r"(addr), "r"(tx) : "memory")

#define MBAR_ARRIVE(addr) \
    asm volatile("mbarrier.arrive.shared.b64 _, [%0];" :: "r"(addr) : "memory")

#define MBAR_WAIT_CL(addr, parity) do {                                        \
    uint32_t _m = (addr); uint32_t _p = (parity); uint32_t _d;                 \
    asm volatile("{\n\t.reg .pred p;\n\t"                                      \
        "mbarrier.try_wait.parity.acquire.cluster.shared::cta.b64 p, [%1], %2;\n\t" \
        "selp.b32 %0, 1, 0, p;\n\t}"                                           \
        : "=r"(_d) : "r"(_m), "r"(_p) : "memory");                             \
    if (!_d) {                                                                 \
        asm volatile("{\n\t.reg .pred P1;\n\t"                                 \
            "W_%=:\n\t"                                                        \
            "mbarrier.try_wait.parity.acquire.cluster.shared::cta.b64 P1, [%0], %1, 0x989680;\n\t" \
            "@P1 bra.uni D_%=;\n\t"                                            \
            "bra.uni W_%=;\n\t"                                                \
            "D_%=:\n\t}" :: "r"(_m), "r"(_p) : "memory");                      \
    }                                                                          \
} while (0)

#define ST_ASYNC_F32(raddr, val, rmbar) \
    asm volatile("st.async.shared::cluster.mbarrier::complete_tx::bytes.b32 [%0], %1, [%2];" \
                 :: "r"(raddr), "r"(__float_as_uint(val)), "r"(rmbar) : "memory")

#define MAPA_U32(out, local, rank) \
    asm("mapa.shared::cluster.u32 %0, %1, %2;" : "=r"(out) : "r"(local), "r"(rank))

// ===========================================================================
// Convert kernels: split fp32 -> bf16 hi/lo, pack K' = [hi | hi | lo]
// ===========================================================================
__global__ __launch_bounds__(192) void convert_x_kernel(const float* __restrict__ x)
{
    const size_t row = blockIdx.x;
    const int t = threadIdx.x;
    float4 v = __ldg((const float4*)(x + row * II) + t);
    __nv_bfloat16 h0 = __float2bfloat16_rn(v.x);
    __nv_bfloat16 h1 = __float2bfloat16_rn(v.y);
    __nv_bfloat16 h2 = __float2bfloat16_rn(v.z);
    __nv_bfloat16 h3 = __float2bfloat16_rn(v.w);
    __nv_bfloat16 l0 = __float2bfloat16_rn(v.x - __bfloat162float(h0));
    __nv_bfloat16 l1 = __float2bfloat16_rn(v.y - __bfloat162float(h1));
    __nv_bfloat16 l2 = __float2bfloat16_rn(v.z - __bfloat162float(h2));
    __nv_bfloat16 l3 = __float2bfloat16_rn(v.w - __bfloat162float(h3));
    __nv_bfloat162 hp0 = __halves2bfloat162(h0, h1);
    __nv_bfloat162 hp1 = __halves2bfloat162(h2, h3);
    __nv_bfloat162 lp0 = __halves2bfloat162(l0, l1);
    __nv_bfloat162 lp1 = __halves2bfloat162(l2, l3);
    __nv_bfloat162* base = (__nv_bfloat162*)(g_ax + row * KP);
    base[t * 2]       = hp0;  base[t * 2 + 1]       = hp1;
    base[384 + t * 2] = hp0;  base[384 + t * 2 + 1] = hp1;
    base[768 + t * 2] = lp0;  base[768 + t * 2 + 1] = lp1;
}

__global__ __launch_bounds__(192) void convert_w_kernel(const float* __restrict__ W)
{
    const size_t row = blockIdx.x;
    const int t = threadIdx.x;
    float4 v = __ldg((const float4*)(W + row * II) + t);
    __nv_bfloat16 h0 = __float2bfloat16_rn(v.x);
    __nv_bfloat16 h1 = __float2bfloat16_rn(v.y);
    __nv_bfloat16 h2 = __float2bfloat16_rn(v.z);
    __nv_bfloat16 h3 = __float2bfloat16_rn(v.w);
    __nv_bfloat16 l0 = __float2bfloat16_rn(v.x - __bfloat162float(h0));
    __nv_bfloat16 l1 = __float2bfloat16_rn(v.y - __bfloat162float(h1));
    __nv_bfloat16 l2 = __float2bfloat16_rn(v.z - __bfloat162float(h2));
    __nv_bfloat16 l3 = __float2bfloat16_rn(v.w - __bfloat162float(h3));
    __nv_bfloat162 hp0 = __halves2bfloat162(h0, h1);
    __nv_bfloat162 hp1 = __halves2bfloat162(h2, h3);
    __nv_bfloat162 lp0 = __halves2bfloat162(l0, l1);
    __nv_bfloat162 lp1 = __halves2bfloat162(l2, l3);
    // B' = [Wh | Wl | Wh] pairs with A' = [xh | xh | xl]
    __nv_bfloat162* base = (__nv_bfloat162*)(g_bx + row * KP);
    base[t * 2]       = hp0;  base[t * 2 + 1]       = hp1;
    base[384 + t * 2] = lp0;  base[384 + t * 2 + 1] = lp1;
    base[768 + t * 2] = hp0;  base[768 + t * 2 + 1] = hp1;
}

// ===========================================================================
// Kernel 1: xg = x @ W_ih^T + b_ih via mma.sync bf16.
// CTA tile 128x256, 512 threads / 16 warps (2 m x 8 n), warp tile 64x32
// (identical to the proven R8 warp tile). 3-stage cp.async pipeline.
// A traffic halves vs BN=128: 3 passes over A' instead of 6.
// ===========================================================================
__global__ __launch_bounds__(512, 1) void gemm_mma_kernel(
    const float* __restrict__ bias)
{
    extern __shared__ __align__(1024) char dsm[];
    __shared__ float s_bias[256];

    const int tid  = threadIdx.x;
    const int lane = tid & 31;
    const int warp = tid >> 5;              // 0..15
    const int wm = warp >> 3;               // 0..1
    const int wn = warp & 7;                // 0..7
    const int n0 = blockIdx.x * 256;        // 0,256,512
    const size_t m0 = (size_t)blockIdx.y * 128;

    const uint32_t smem_base = smem_u32(dsm);

    if (tid < 256) s_bias[tid] = __ldg(bias + n0 + tid);

    const char* gA = (const char*)(g_ax) + m0 * KPB;
    const char* gB = (const char*)(g_bx) + (size_t)n0 * KPB;

    // per chunk: A 1024 segs (2/thread), B 2048 segs (4/thread)
    auto issue_loads = [&](int slot, int kbyte) {
        const uint32_t stgA = smem_base + slot * STG_BYTES;
        const uint32_t stgB = stgA + 16384;
#pragma unroll
        for (int i = 0; i < 2; i++) {
            int seg = tid + i * 512;            // 0..1023
            int r = seg >> 3, c = seg & 7;
            uint32_t off = (uint32_t)(r * 128 + ((c ^ (r & 7)) << 4));
            cpa16(stgA + off, gA + (size_t)r * KPB + kbyte + c * 16);
        }
#pragma unroll
        for (int i = 0; i < 4; i++) {
            int seg = tid + i * 512;            // 0..2047
            int r = seg >> 3, c = seg & 7;
            uint32_t off = (uint32_t)(r * 128 + ((c ^ (r & 7)) << 4));
            cpa16(stgB + off, gB + (size_t)r * KPB + kbyte + c * 16);
        }
    };

    const int lrow = (lane & 7) + ((lane >> 3) & 1) * 8;
    const int cp   = lane >> 4;
    const int arow = wm * 64 + lrow;
    const int brow = wn * 32 + lrow;        // 0..255

    float acc[4][4][4];
#pragma unroll
    for (int f = 0; f < 4; f++)
#pragma unroll
        for (int g = 0; g < 4; g++)
#pragma unroll
            for (int r = 0; r < 4; r++) acc[f][g][r] = 0.0f;

    issue_loads(0, 0);
    asm volatile("cp.async.commit_group;" ::: "memory");
    issue_loads(1, 128);
    asm volatile("cp.async.commit_group;" ::: "memory");

    for (int c = 0; c < NCHUNK; c++) {
        const int lc = c + 2;
        if (lc < NCHUNK) issue_loads(lc % NSTG, lc * 128);
        asm volatile("cp.async.commit_group;" ::: "memory");
        asm volatile("cp.async.wait_group 2;" ::: "memory");
        __syncthreads();

        const uint32_t stgA = smem_base + (c % NSTG) * STG_BYTES;
        const uint32_t stgB = stgA + 16384;

#pragma unroll
        for (int s = 0; s < 4; s++) {
            const int ach = ((2 * s + cp) ^ (arow & 7)) << 4;
            const int bch = ((2 * s + cp) ^ (brow & 7)) << 4;
            uint32_t a[4][4];
            uint32_t b[2][4];
#pragma unroll
            for (int f = 0; f < 4; f++)
                LDSM_X4(a[f], stgA + (uint32_t)((arow + f * 16) * 128 + ach));
#pragma unroll
            for (int g2 = 0; g2 < 2; g2++)
                LDSM_X4(b[g2], stgB + (uint32_t)((brow + g2 * 16) * 128 + bch));
#pragma unroll
            for (int f = 0; f < 4; f++) {
#pragma unroll
                for (int g = 0; g < 4; g++)
                    MMA_16816(acc[f][g], a[f], b[g >> 1][g & 1], b[g >> 1][(g & 1) + 2]);
            }
        }
        __syncthreads();
    }

    const int qrow = lane >> 2;
    const int qcol = (lane & 3) * 2;
#pragma unroll
    for (int f = 0; f < 4; f++) {
        const size_t gr = m0 + wm * 64 + f * 16 + qrow;
#pragma unroll
        for (int g = 0; g < 4; g++) {
            const int lc = wn * 32 + g * 8 + qcol;
            const float b0 = s_bias[lc], b1 = s_bias[lc + 1];
            float* p0 = g_xg + gr * G3 + n0 + lc;
            float* p1 = p0 + 8 * G3;
            *(float2*)p0 = make_float2(acc[f][g][0] + b0, acc[f][g][1] + b1);
            *(float2*)p1 = make_float2(acc[f][g][2] + b0, acc[f][g][3] + b1);
        }
    }
}

// ===========================================================================
// Kernel 2: GRU scan — EXACT R11 (known good, 2053 us):
// register weights, k-quarter split, local STS + 3x st.async exchange,
// decay exp precomputed in prefetch window, clamp-free gate math.
// ===========================================================================
#define HQ  68                // hbuf quarter stride (floats)
#define HBS (4 * HQ)          // per-batch stride = 272

__device__ __forceinline__ float fast_sig(float x) {
    return __fdividef(1.f, 1.f + __expf(-x));
}
__device__ __forceinline__ float fast_tanh(float x) {
    return 1.f - __fdividef(2.f, __expf(2.f * x) + 1.f);
}

__global__ void __cluster_dims__(4, 1, 1) __launch_bounds__(256, 1)
scan_kernel(const float* __restrict__ rel_pos, const float* __restrict__ alpha,
            const float* __restrict__ W_hh, const float* __restrict__ b_hh)
{
    __shared__ __align__(16) float hbuf[2 * 4 * HBS];   // [parity][b][4*68]
    __shared__ __align__(8) unsigned long long s_mbar[2];

    cg::cluster_group cluster = cg::this_cluster();
    const int crank = cluster.block_rank();     // 0..3
    const int cid   = blockIdx.x >> 2;          // 0..31
    const int tid   = threadIdx.x;
    const int u  = tid >> 2;                    // 0..63
    const int kq = tid & 3;                     // 0..3 (k-quarter, also batch)

    if (tid == 0) {
        MBAR_INIT(smem_u32(&s_mbar[0]), 256);
        MBAR_INIT(smem_u32(&s_mbar[1]), 256);
        asm volatile("fence.mbarrier_init.release.cluster;" ::: "memory");
    }
    cluster.sync();

    // ---- load this thread's weight slice into registers ----
    ull wr[32], wz[32], wn[32];
    {
        const ulonglong2* p0 = (const ulonglong2*)(W_hh +
            (size_t)(0 * 256 + crank * 64 + u) * HH + kq * 64);
        const ulonglong2* p1 = (const ulonglong2*)(W_hh +
            (size_t)(1 * 256 + crank * 64 + u) * HH + kq * 64);
        const ulonglong2* p2 = (const ulonglong2*)(W_hh +
            (size_t)(2 * 256 + crank * 64 + u) * HH + kq * 64);
#pragma unroll
        for (int i = 0; i < 16; i++) {
            ulonglong2 va = __ldg(p0 + i); wr[2 * i] = va.x; wr[2 * i + 1] = va.y;
            ulonglong2 vb = __ldg(p1 + i); wz[2 * i] = vb.x; wz[2 * i + 1] = vb.y;
            ulonglong2 vc = __ldg(p2 + i); wn[2 * i] = vc.x; wn[2 * i + 1] = vc.y;
        }
    }
    const float bias_r = __ldg(b_hh + 0 * 256 + crank * 64 + u);
    const float bias_z = __ldg(b_hh + 1 * 256 + crank * 64 + u);
    const float bias_n = __ldg(b_hh + 2 * 256 + crank * 64 + u);

    const int batch = cid * 4 + kq;             // this thread's gate batch
    const float a = fabsf(__ldg(alpha));

    const float* rp = rel_pos + (size_t)batch * SS;
    const float* xg_base = g_xg + ((size_t)batch * SS) * G3 + crank * 64 + u;
    float* hs_base = g_hs + ((size_t)batch * SS) * HH + crank * 64 + u;

    // own slot (local STS) + 3 remote targets (st.async)
    float* lown = &hbuf[kq * HBS + crank * HQ + u];
    uint32_t rhb[3], rmb[3];
    {
        uint32_t lslot = smem_u32(lown);
        uint32_t lmbar = smem_u32(&s_mbar[0]);
        int idx = 0;
#pragma unroll
        for (int r = 0; r < 4; r++) {
            if (r != crank) {
                MAPA_U32(rhb[idx], lslot, r);
                MAPA_U32(rmb[idx], lmbar, r);
                idx++;
            }
        }
    }
    const uint32_t lmb = smem_u32(&s_mbar[0]);

    // prefetch t = 0
    float rpt = __ldg(rp);
    float xr = __ldg(xg_base), xz = __ldg(xg_base + 256), xn = __ldg(xg_base + 512);
    float dec = __expf(-a * rpt);               // dt(0) = rp[0] - 0

    float h = 0.0f;

    for (int t = 0; t < SS; t++) {
        const uint32_t ph    = (uint32_t)(t & 1);
        const int      poff  = (int)ph * (4 * HBS);     // float offset
        const uint32_t poffB = ph * (uint32_t)(4 * HBS * 4);
        const uint32_t wp    = (uint32_t)((t >> 1) & 1);

        // decay (exp precomputed) + local STS + remote async broadcast
        float hd = h * dec;
        lown[poff] = hd;
        if (tid == 0) MBAR_EXPECT_TX(lmb + ph * 8, 3072u);
        else          MBAR_ARRIVE(lmb + ph * 8);
        ST_ASYNC_F32(rhb[0] + poffB, hd, rmb[0] + ph * 8);
        ST_ASYNC_F32(rhb[1] + poffB, hd, rmb[1] + ph * 8);
        ST_ASYNC_F32(rhb[2] + poffB, hd, rmb[2] + ph * 8);

        // prefetch next xg / rel_pos / decay while exchange is in flight
        const int tn = (t + 1 < SS) ? (t + 1) : (SS - 1);
        const float* xgn = xg_base + (size_t)tn * G3;
        float xr_n = __ldg(xgn), xz_n = __ldg(xgn + 256), xn_n = __ldg(xgn + 512);
        float rpt_n = __ldg(rp + tn);
        float dec_n = __expf(-a * (rpt_n - rpt));

        MBAR_WAIT_CL(lmb + ph * 8, wp);

        // k-quarter matvec for all 4 batches (weights in registers)
        float hr = 0.f, hz = 0.f, hnv = 0.f;
#pragma unroll
        for (int b = 0; b < 4; b++) {
            const ulonglong2* hb =
                (const ulonglong2*)(hbuf + poff + b * HBS + kq * HQ);
            ull ar = 0ull, az = 0ull, an = 0ull;
#pragma unroll
            for (int i = 0; i < 16; i++) {
                ulonglong2 hv = hb[i];
                FMA2(ar, wr[2 * i], hv.x); FMA2(ar, wr[2 * i + 1], hv.y);
                FMA2(az, wz[2 * i], hv.x); FMA2(az, wz[2 * i + 1], hv.y);
                FMA2(an, wn[2 * i], hv.x); FMA2(an, wn[2 * i + 1], hv.y);
            }
            float2 f;
            float pr, pz, pn;
            f = *(float2*)&ar; pr = f.x + f.y;
            f = *(float2*)&az; pz = f.x + f.y;
            f = *(float2*)&an; pn = f.x + f.y;
            pr += __shfl_xor_sync(0xFFFFFFFFu, pr, 1);
            pz += __shfl_xor_sync(0xFFFFFFFFu, pz, 1);
            pn += __shfl_xor_sync(0xFFFFFFFFu, pn, 1);
            pr += __shfl_xor_sync(0xFFFFFFFFu, pr, 2);
            pz += __shfl_xor_sync(0xFFFFFFFFu, pz, 2);
            pn += __shfl_xor_sync(0xFFFFFFFFu, pn, 2);
            if (kq == b) { hr = pr; hz = pz; hnv = pn; }
        }

        float r = fast_sig(xr + hr + bias_r);
        float z = fast_sig(xz + hz + bias_z);
        float n = fast_tanh(xn + (hnv + bias_n) * r);
        h = n + z * (hd - n);

        hs_base[(size_t)t * HH] = h;

        xr = xr_n; xz = xz_n; xn = xn_n; rpt = rpt_n; dec = dec_n;
    }

    // no CTA may exit while peers might still st.async into its smem
    cluster.sync();
}

// ===========================================================================
// Kernel 3: out = hs @ W_fc^T + b_fc.
// ===========================================================================
__global__ __launch_bounds__(256) void fc_kernel(
    const float* __restrict__ W_fc, const float* __restrict__ b_fc,
    float* __restrict__ out)
{
    __shared__ float Wsm[OO * HH];
    __shared__ float bsm[OO];
    const int tid = threadIdx.x;
    for (int i = tid; i < OO * HH; i += 256) Wsm[i] = W_fc[i];
    if (tid < OO) bsm[tid] = b_fc[tid];
    __syncthreads();

    const int warp = tid >> 5, lane = tid & 31;
    const size_t m = (size_t)blockIdx.x * 8 + warp;

    const float4* hp = (const float4*)(g_hs + m * HH + lane * 8);
    float4 hv0 = hp[0], hv1 = hp[1];

    float acc[OO];
#pragma unroll
    for (int o = 0; o < OO; o++) {
        const float* w = Wsm + o * HH + lane * 8;
        float4 w0 = *(const float4*)w;
        float4 w1 = *(const float4*)(w + 4);
        float s;
        s = hv0.x * w0.x;
        s = fmaf(hv0.y, w0.y, s);
        s = fmaf(hv0.z, w0.z, s);
        s = fmaf(hv0.w, w0.w, s);
        s = fmaf(hv1.x, w1.x, s);
        s = fmaf(hv1.y, w1.y, s);
        s = fmaf(hv1.z, w1.z, s);
        s = fmaf(hv1.w, w1.w, s);
        acc[o] = s;
    }
#pragma unroll
    for (int sft = 16; sft; sft >>= 1)
#pragma unroll
        for (int o = 0; o < OO; o++)
            acc[o] += __shfl_xor_sync(0xFFFFFFFFu, acc[o], sft);

    if (lane == 0) {
#pragma unroll
        for (int o = 0; o < OO; o++)
            out[m * OO + o] = acc[o] + bsm[o];
    }
}

// ===========================================================================
// Launch
// ===========================================================================
extern "C" void kernel_launch(void* const* d_in, const int* in_sizes, int n_in,
                              void* d_out, int out_size)
{
    const float* x       = (const float*)d_in[0];
    const float* rel_pos = (const float*)d_in[1];
    const float* alpha   = (const float*)d_in[2];
    const float* W_ih    = (const float*)d_in[3];
    const float* b_ih    = (const float*)d_in[4];
    const float* W_hh    = (const float*)d_in[5];
    const float* b_hh    = (const float*)d_in[6];
    const float* W_fc    = (const float*)d_in[7];
    const float* b_fc    = (const float*)d_in[8];
    float* out = (float*)d_out;

    (void)in_sizes; (void)n_in; (void)out_size;

    // 0) bf16 hi/lo packing
    convert_x_kernel<<<MM, 192>>>(x);
    convert_w_kernel<<<G3, 192>>>(W_ih);

    // 1) Input projection via mma.sync (3 n-tiles x 1024 m-tiles, 512 thr)
    cudaFuncSetAttribute(gemm_mma_kernel,
                         cudaFuncAttributeMaxDynamicSharedMemorySize,
                         NSTG * STG_BYTES);
    dim3 ggrid(3, 1024);
    gemm_mma_kernel<<<ggrid, 512, NSTG * STG_BYTES>>>(b_ih);

    // 2) Scan (4-CTA clusters, register weights, local STS + 3x st.async)
    scan_kernel<<<128, 256>>>(rel_pos, alpha, W_hh, b_hh);

    // 3) Output FC
    fc_kernel<<<MM / 8, 256>>>(W_fc, b_fc, out);
}

// round 13
// speedup vs baseline: 1.0385x; 1.0385x over previous
#include <cuda_runtime.h>
#include <cuda_bf16.h>
#include <cooperative_groups.h>
#include <cstdint>

namespace cg = cooperative_groups;

// Problem constants
#define BB 128          // batch
#define SS 1024         // seq
#define II 768          // input dim
#define HH 256          // hidden
#define OO 6            // output
#define MM (BB * SS)    // 131072 rows
#define G3 (3 * HH)     // 768 gate rows

#define KP   2304       // packed K' = 3*768 (bf16 hi|hi|lo)
#define KPB  (KP * 2)   // 4608 bytes per packed row
#define NCHUNK (KP / 64)    // 36
#define NSTG 3
#define STG_BYTES 32768     // A 16KB + B 16KB

typedef unsigned long long ull;

// ---------------------------------------------------------------------------
// Scratch (device globals — allocation-free rule)
// ---------------------------------------------------------------------------
__device__ __align__(128) float g_xg[(size_t)MM * G3];           // [M, 768]
__device__ __align__(128) float g_hs[(size_t)MM * HH];           // [M, 256]
__device__ __align__(128) __nv_bfloat16 g_ax[(size_t)MM * KP];   // packed A'
__device__ __align__(128) __nv_bfloat16 g_bx[(size_t)G3 * KP];   // packed B'

// ---------------------------------------------------------------------------
// Generic-PTX helpers
// ---------------------------------------------------------------------------
__device__ __forceinline__ uint32_t smem_u32(const void* p) {
    uint32_t r;
    asm("{ .reg .u64 t; cvta.to.shared.u64 t, %1; cvt.u32.u64 %0, t; }"
        : "=r"(r) : "l"(p));
    return r;
}

__device__ __forceinline__ void cpa16(uint32_t saddr, const char* g) {
    asm volatile("cp.async.cg.shared.global [%0], [%1], 16;" :: "r"(saddr), "l"(g));
}

#define LDSM_X4(r, addr) \
    asm volatile("ldmatrix.sync.aligned.m8n8.x4.shared.b16 {%0,%1,%2,%3}, [%4];" \
                 : "=r"((r)[0]), "=r"((r)[1]), "=r"((r)[2]), "=r"((r)[3]) : "r"(addr))

#define MMA_16816(d, a, b0, b1) \
    asm volatile("mma.sync.aligned.m16n8k16.row.col.f32.bf16.bf16.f32 " \
                 "{%0,%1,%2,%3}, {%4,%5,%6,%7}, {%8,%9}, {%0,%1,%2,%3};" \
                 : "+f"((d)[0]), "+f"((d)[1]), "+f"((d)[2]), "+f"((d)[3]) \
                 : "r"((a)[0]), "r"((a)[1]), "r"((a)[2]), "r"((a)[3]), \
                   "r"(b0), "r"(b1))

#define FMA2(acc, a, b) \
    asm("fma.rn.f32x2 %0, %1, %2, %0;" : "+l"(acc) : "l"(a), "l"(b))

#define MBAR_INIT(addr, cnt) \
    asm volatile("mbarrier.init.shared.b64 [%0], %1;" :: "r"(addr), "r"(cnt) : "memory")

#define MBAR_EXPECT_TX(addr, tx) \
    asm volatile("mbarrier.arrive.expect_tx.shared.b64 _, [%0], %1;" \
                 :: "r"(addr), "r"(tx) : "memory")

#define MBAR_ARRIVE(addr) \
    asm volatile("mbarrier.arrive.shared.b64 _, [%0];" :: "r"(addr) : "memory")

#define MBAR_WAIT_CL(addr, parity) do {                                        \
    uint32_t _m = (addr); uint32_t _p = (parity); uint32_t _d;                 \
    asm volatile("{\n\t.reg .pred p;\n\t"                                      \
        "mbarrier.try_wait.parity.acquire.cluster.shared::cta.b64 p, [%1], %2;\n\t" \
        "selp.b32 %0, 1, 0, p;\n\t}"                                           \
        : "=r"(_d) : "r"(_m), "r"(_p) : "memory");                             \
    if (!_d) {                                                                 \
        asm volatile("{\n\t.reg .pred P1;\n\t"                                 \
            "W_%=:\n\t"                                                        \
            "mbarrier.try_wait.parity.acquire.cluster.shared::cta.b64 P1, [%0], %1, 0x989680;\n\t" \
            "@P1 bra.uni D_%=;\n\t"                                            \
            "bra.uni W_%=;\n\t"                                                \
            "D_%=:\n\t}" :: "r"(_m), "r"(_p) : "memory");                      \
    }                                                                          \
} while (0)

#define ST_ASYNC_F32(raddr, val, rmbar) \
    asm volatile("st.async.shared::cluster.mbarrier::complete_tx::bytes.b32 [%0], %1, [%2];" \
                 :: "r"(raddr), "r"(__float_as_uint(val)), "r"(rmbar) : "memory")

#define MAPA_U32(out, local, rank) \
    asm("mapa.shared::cluster.u32 %0, %1, %2;" : "=r"(out) : "r"(local), "r"(rank))

// ===========================================================================
// Convert kernels: split fp32 -> bf16 hi/lo, pack K' = [hi | hi | lo]
// ===========================================================================
__global__ __launch_bounds__(192) void convert_x_kernel(const float* __restrict__ x)
{
    const size_t row = blockIdx.x;
    const int t = threadIdx.x;
    float4 v = __ldg((const float4*)(x + row * II) + t);
    __nv_bfloat16 h0 = __float2bfloat16_rn(v.x);
    __nv_bfloat16 h1 = __float2bfloat16_rn(v.y);
    __nv_bfloat16 h2 = __float2bfloat16_rn(v.z);
    __nv_bfloat16 h3 = __float2bfloat16_rn(v.w);
    __nv_bfloat16 l0 = __float2bfloat16_rn(v.x - __bfloat162float(h0));
    __nv_bfloat16 l1 = __float2bfloat16_rn(v.y - __bfloat162float(h1));
    __nv_bfloat16 l2 = __float2bfloat16_rn(v.z - __bfloat162float(h2));
    __nv_bfloat16 l3 = __float2bfloat16_rn(v.w - __bfloat162float(h3));
    __nv_bfloat162 hp0 = __halves2bfloat162(h0, h1);
    __nv_bfloat162 hp1 = __halves2bfloat162(h2, h3);
    __nv_bfloat162 lp0 = __halves2bfloat162(l0, l1);
    __nv_bfloat162 lp1 = __halves2bfloat162(l2, l3);
    __nv_bfloat162* base = (__nv_bfloat162*)(g_ax + row * KP);
    base[t * 2]       = hp0;  base[t * 2 + 1]       = hp1;
    base[384 + t * 2] = hp0;  base[384 + t * 2 + 1] = hp1;
    base[768 + t * 2] = lp0;  base[768 + t * 2 + 1] = lp1;
}

__global__ __launch_bounds__(192) void convert_w_kernel(const float* __restrict__ W)
{
    const size_t row = blockIdx.x;
    const int t = threadIdx.x;
    float4 v = __ldg((const float4*)(W + row * II) + t);
    __nv_bfloat16 h0 = __float2bfloat16_rn(v.x);
    __nv_bfloat16 h1 = __float2bfloat16_rn(v.y);
    __nv_bfloat16 h2 = __float2bfloat16_rn(v.z);
    __nv_bfloat16 h3 = __float2bfloat16_rn(v.w);
    __nv_bfloat16 l0 = __float2bfloat16_rn(v.x - __bfloat162float(h0));
    __nv_bfloat16 l1 = __float2bfloat16_rn(v.y - __bfloat162float(h1));
    __nv_bfloat16 l2 = __float2bfloat16_rn(v.z - __bfloat162float(h2));
    __nv_bfloat16 l3 = __float2bfloat16_rn(v.w - __bfloat162float(h3));
    __nv_bfloat162 hp0 = __halves2bfloat162(h0, h1);
    __nv_bfloat162 hp1 = __halves2bfloat162(h2, h3);
    __nv_bfloat162 lp0 = __halves2bfloat162(l0, l1);
    __nv_bfloat162 lp1 = __halves2bfloat162(l2, l3);
    // B' = [Wh | Wl | Wh] pairs with A' = [xh | xh | xl]
    __nv_bfloat162* base = (__nv_bfloat162*)(g_bx + row * KP);
    base[t * 2]       = hp0;  base[t * 2 + 1]       = hp1;
    base[384 + t * 2] = lp0;  base[384 + t * 2 + 1] = lp1;
    base[768 + t * 2] = hp0;  base[768 + t * 2 + 1] = hp1;
}

// ===========================================================================
// Kernel 1: xg = x @ W_ih^T + b_ih via mma.sync bf16 (R11 config: BN=128,
// 256 threads, 96KB smem -> 2 CTAs/SM) with single-sync pipeline:
//   wait_group 1 ; __syncthreads ; issue(c+2) ; compute(c)
// Safety: slot (c+2)%3 was last read in compute(c-1); every thread passed
// that compute before this iteration's sync, so the slot is free to write.
// ===========================================================================
__global__ __launch_bounds__(256, 2) void gemm_mma_kernel(
    const float* __restrict__ bias)
{
    extern __shared__ __align__(1024) char dsm[];
    __shared__ float s_bias[128];

    const int tid  = threadIdx.x;
    const int lane = tid & 31;
    const int warp = tid >> 5;
    const int wm = warp >> 2;
    const int wn = warp & 3;
    const int n0 = blockIdx.x * 128;
    const size_t m0 = (size_t)blockIdx.y * 128;

    const uint32_t smem_base = smem_u32(dsm);

    if (tid < 128) s_bias[tid] = __ldg(bias + n0 + tid);

    const char* gA = (const char*)(g_ax) + m0 * KPB;
    const char* gB = (const char*)(g_bx) + (size_t)n0 * KPB;

    auto issue_loads = [&](int slot, int kbyte) {
        const uint32_t stgA = smem_base + slot * STG_BYTES;
        const uint32_t stgB = stgA + 16384;
#pragma unroll
        for (int i = 0; i < 4; i++) {
            int seg = tid + i * 256;
            int r = seg >> 3, c = seg & 7;
            uint32_t off = (uint32_t)(r * 128 + ((c ^ (r & 7)) << 4));
            const size_t goff = (size_t)r * KPB + kbyte + c * 16;
            cpa16(stgA + off, gA + goff);
            cpa16(stgB + off, gB + goff);
        }
    };

    const int lrow = (lane & 7) + ((lane >> 3) & 1) * 8;
    const int cp   = lane >> 4;
    const int arow = wm * 64 + lrow;
    const int brow = wn * 32 + lrow;

    float acc[4][4][4];
#pragma unroll
    for (int f = 0; f < 4; f++)
#pragma unroll
        for (int g = 0; g < 4; g++)
#pragma unroll
            for (int r = 0; r < 4; r++) acc[f][g][r] = 0.0f;

    issue_loads(0, 0);
    asm volatile("cp.async.commit_group;" ::: "memory");
    issue_loads(1, 128);
    asm volatile("cp.async.commit_group;" ::: "memory");

    for (int c = 0; c < NCHUNK; c++) {
        // chunk c resident when pending groups <= 1 (c+1 may be in flight)
        asm volatile("cp.async.wait_group 1;" ::: "memory");
        __syncthreads();

        const int lc = c + 2;
        if (lc < NCHUNK) issue_loads(lc % NSTG, lc * 128);
        asm volatile("cp.async.commit_group;" ::: "memory");

        const uint32_t stgA = smem_base + (c % NSTG) * STG_BYTES;
        const uint32_t stgB = stgA + 16384;

#pragma unroll
        for (int s = 0; s < 4; s++) {
            const int ach = ((2 * s + cp) ^ (arow & 7)) << 4;
            const int bch = ((2 * s + cp) ^ (brow & 7)) << 4;
            uint32_t a[4][4];
            uint32_t b[2][4];
#pragma unroll
            for (int f = 0; f < 4; f++)
                LDSM_X4(a[f], stgA + (uint32_t)((arow + f * 16) * 128 + ach));
#pragma unroll
            for (int g2 = 0; g2 < 2; g2++)
                LDSM_X4(b[g2], stgB + (uint32_t)((brow + g2 * 16) * 128 + bch));
#pragma unroll
            for (int f = 0; f < 4; f++) {
#pragma unroll
                for (int g = 0; g < 4; g++)
                    MMA_16816(acc[f][g], a[f], b[g >> 1][g & 1], b[g >> 1][(g & 1) + 2]);
            }
        }
    }

    const int qrow = lane >> 2;
    const int qcol = (lane & 3) * 2;
#pragma unroll
    for (int f = 0; f < 4; f++) {
        const size_t gr = m0 + wm * 64 + f * 16 + qrow;
#pragma unroll
        for (int g = 0; g < 4; g++) {
            const int lc = wn * 32 + g * 8 + qcol;
            const float b0 = s_bias[lc], b1 = s_bias[lc + 1];
            float* p0 = g_xg + gr * G3 + n0 + lc;
            float* p1 = p0 + 8 * G3;
            *(float2*)p0 = make_float2(acc[f][g][0] + b0, acc[f][g][1] + b1);
            *(float2*)p1 = make_float2(acc[f][g][2] + b0, acc[f][g][3] + b1);
        }
    }
}

// ===========================================================================
// Kernel 2: GRU scan — EXACT R11 (best known, ~2045 us):
// register weights, k-quarter split, local STS + 3x st.async exchange,
// decay exp precomputed in prefetch window, clamp-free gate math.
// ===========================================================================
#define HQ  68                // hbuf quarter stride (floats)
#define HBS (4 * HQ)          // per-batch stride = 272

__device__ __forceinline__ float fast_sig(float x) {
    return __fdividef(1.f, 1.f + __expf(-x));
}
__device__ __forceinline__ float fast_tanh(float x) {
    return 1.f - __fdividef(2.f, __expf(2.f * x) + 1.f);
}

__global__ void __cluster_dims__(4, 1, 1) __launch_bounds__(256, 1)
scan_kernel(const float* __restrict__ rel_pos, const float* __restrict__ alpha,
            const float* __restrict__ W_hh, const float* __restrict__ b_hh)
{
    __shared__ __align__(16) float hbuf[2 * 4 * HBS];   // [parity][b][4*68]
    __shared__ __align__(8) unsigned long long s_mbar[2];

    cg::cluster_group cluster = cg::this_cluster();
    const int crank = cluster.block_rank();     // 0..3
    const int cid   = blockIdx.x >> 2;          // 0..31
    const int tid   = threadIdx.x;
    const int u  = tid >> 2;                    // 0..63
    const int kq = tid & 3;                     // 0..3 (k-quarter, also batch)

    if (tid == 0) {
        MBAR_INIT(smem_u32(&s_mbar[0]), 256);
        MBAR_INIT(smem_u32(&s_mbar[1]), 256);
        asm volatile("fence.mbarrier_init.release.cluster;" ::: "memory");
    }
    cluster.sync();

    // ---- load this thread's weight slice into registers ----
    ull wr[32], wz[32], wn[32];
    {
        const ulonglong2* p0 = (const ulonglong2*)(W_hh +
            (size_t)(0 * 256 + crank * 64 + u) * HH + kq * 64);
        const ulonglong2* p1 = (const ulonglong2*)(W_hh +
            (size_t)(1 * 256 + crank * 64 + u) * HH + kq * 64);
        const ulonglong2* p2 = (const ulonglong2*)(W_hh +
            (size_t)(2 * 256 + crank * 64 + u) * HH + kq * 64);
#pragma unroll
        for (int i = 0; i < 16; i++) {
            ulonglong2 va = __ldg(p0 + i); wr[2 * i] = va.x; wr[2 * i + 1] = va.y;
            ulonglong2 vb = __ldg(p1 + i); wz[2 * i] = vb.x; wz[2 * i + 1] = vb.y;
            ulonglong2 vc = __ldg(p2 + i); wn[2 * i] = vc.x; wn[2 * i + 1] = vc.y;
        }
    }
    const float bias_r = __ldg(b_hh + 0 * 256 + crank * 64 + u);
    const float bias_z = __ldg(b_hh + 1 * 256 + crank * 64 + u);
    const float bias_n = __ldg(b_hh + 2 * 256 + crank * 64 + u);

    const int batch = cid * 4 + kq;             // this thread's gate batch
    const float a = fabsf(__ldg(alpha));

    const float* rp = rel_pos + (size_t)batch * SS;
    const float* xg_base = g_xg + ((size_t)batch * SS) * G3 + crank * 64 + u;
    float* hs_base = g_hs + ((size_t)batch * SS) * HH + crank * 64 + u;

    // own slot (local STS) + 3 remote targets (st.async)
    float* lown = &hbuf[kq * HBS + crank * HQ + u];
    uint32_t rhb[3], rmb[3];
    {
        uint32_t lslot = smem_u32(lown);
        uint32_t lmbar = smem_u32(&s_mbar[0]);
        int idx = 0;
#pragma unroll
        for (int r = 0; r < 4; r++) {
            if (r != crank) {
                MAPA_U32(rhb[idx], lslot, r);
                MAPA_U32(rmb[idx], lmbar, r);
                idx++;
            }
        }
    }
    const uint32_t lmb = smem_u32(&s_mbar[0]);

    // prefetch t = 0
    float rpt = __ldg(rp);
    float xr = __ldg(xg_base), xz = __ldg(xg_base + 256), xn = __ldg(xg_base + 512);
    float dec = __expf(-a * rpt);               // dt(0) = rp[0] - 0

    float h = 0.0f;

    for (int t = 0; t < SS; t++) {
        const uint32_t ph    = (uint32_t)(t & 1);
        const int      poff  = (int)ph * (4 * HBS);     // float offset
        const uint32_t poffB = ph * (uint32_t)(4 * HBS * 4);
        const uint32_t wp    = (uint32_t)((t >> 1) & 1);

        // decay (exp precomputed) + local STS + remote async broadcast
        float hd = h * dec;
        lown[poff] = hd;
        if (tid == 0) MBAR_EXPECT_TX(lmb + ph * 8, 3072u);
        else          MBAR_ARRIVE(lmb + ph * 8);
        ST_ASYNC_F32(rhb[0] + poffB, hd, rmb[0] + ph * 8);
        ST_ASYNC_F32(rhb[1] + poffB, hd, rmb[1] + ph * 8);
        ST_ASYNC_F32(rhb[2] + poffB, hd, rmb[2] + ph * 8);

        // prefetch next xg / rel_pos / decay while exchange is in flight
        const int tn = (t + 1 < SS) ? (t + 1) : (SS - 1);
        const float* xgn = xg_base + (size_t)tn * G3;
        float xr_n = __ldg(xgn), xz_n = __ldg(xgn + 256), xn_n = __ldg(xgn + 512);
        float rpt_n = __ldg(rp + tn);
        float dec_n = __expf(-a * (rpt_n - rpt));

        MBAR_WAIT_CL(lmb + ph * 8, wp);

        // k-quarter matvec for all 4 batches (weights in registers)
        float hr = 0.f, hz = 0.f, hnv = 0.f;
#pragma unroll
        for (int b = 0; b < 4; b++) {
            const ulonglong2* hb =
                (const ulonglong2*)(hbuf + poff + b * HBS + kq * HQ);
            ull ar = 0ull, az = 0ull, an = 0ull;
#pragma unroll
            for (int i = 0; i < 16; i++) {
                ulonglong2 hv = hb[i];
                FMA2(ar, wr[2 * i], hv.x); FMA2(ar, wr[2 * i + 1], hv.y);
                FMA2(az, wz[2 * i], hv.x); FMA2(az, wz[2 * i + 1], hv.y);
                FMA2(an, wn[2 * i], hv.x); FMA2(an, wn[2 * i + 1], hv.y);
            }
            float2 f;
            float pr, pz, pn;
            f = *(float2*)&ar; pr = f.x + f.y;
            f = *(float2*)&az; pz = f.x + f.y;
            f = *(float2*)&an; pn = f.x + f.y;
            pr += __shfl_xor_sync(0xFFFFFFFFu, pr, 1);
            pz += __shfl_xor_sync(0xFFFFFFFFu, pz, 1);
            pn += __shfl_xor_sync(0xFFFFFFFFu, pn, 1);
            pr += __shfl_xor_sync(0xFFFFFFFFu, pr, 2);
            pz += __shfl_xor_sync(0xFFFFFFFFu, pz, 2);
            pn += __shfl_xor_sync(0xFFFFFFFFu, pn, 2);
            if (kq == b) { hr = pr; hz = pz; hnv = pn; }
        }

        float r = fast_sig(xr + hr + bias_r);
        float z = fast_sig(xz + hz + bias_z);
        float n = fast_tanh(xn + (hnv + bias_n) * r);
        h = n + z * (hd - n);

        hs_base[(size_t)t * HH] = h;

        xr = xr_n; xz = xz_n; xn = xn_n; rpt = rpt_n; dec = dec_n;
    }

    // no CTA may exit while peers might still st.async into its smem
    cluster.sync();
}

// ===========================================================================
// Kernel 3: out = hs @ W_fc^T + b_fc.
// ===========================================================================
__global__ __launch_bounds__(256) void fc_kernel(
    const float* __restrict__ W_fc, const float* __restrict__ b_fc,
    float* __restrict__ out)
{
    __shared__ float Wsm[OO * HH];
    __shared__ float bsm[OO];
    const int tid = threadIdx.x;
    for (int i = tid; i < OO * HH; i += 256) Wsm[i] = W_fc[i];
    if (tid < OO) bsm[tid] = b_fc[tid];
    __syncthreads();

    const int warp = tid >> 5, lane = tid & 31;
    const size_t m = (size_t)blockIdx.x * 8 + warp;

    const float4* hp = (const float4*)(g_hs + m * HH + lane * 8);
    float4 hv0 = hp[0], hv1 = hp[1];

    float acc[OO];
#pragma unroll
    for (int o = 0; o < OO; o++) {
        const float* w = Wsm + o * HH + lane * 8;
        float4 w0 = *(const float4*)w;
        float4 w1 = *(const float4*)(w + 4);
        float s;
        s = hv0.x * w0.x;
        s = fmaf(hv0.y, w0.y, s);
        s = fmaf(hv0.z, w0.z, s);
        s = fmaf(hv0.w, w0.w, s);
        s = fmaf(hv1.x, w1.x, s);
        s = fmaf(hv1.y, w1.y, s);
        s = fmaf(hv1.z, w1.z, s);
        s = fmaf(hv1.w, w1.w, s);
        acc[o] = s;
    }
#pragma unroll
    for (int sft = 16; sft; sft >>= 1)
#pragma unroll
        for (int o = 0; o < OO; o++)
            acc[o] += __shfl_xor_sync(0xFFFFFFFFu, acc[o], sft);

    if (lane == 0) {
#pragma unroll
        for (int o = 0; o < OO; o++)
            out[m * OO + o] = acc[o] + bsm[o];
    }
}

// ===========================================================================
// Launch
// ===========================================================================
extern "C" void kernel_launch(void* const* d_in, const int* in_sizes, int n_in,
                              void* d_out, int out_size)
{
    const float* x       = (const float*)d_in[0];
    const float* rel_pos = (const float*)d_in[1];
    const float* alpha   = (const float*)d_in[2];
    const float* W_ih    = (const float*)d_in[3];
    const float* b_ih    = (const float*)d_in[4];
    const float* W_hh    = (const float*)d_in[5];
    const float* b_hh    = (const float*)d_in[6];
    const float* W_fc    = (const float*)d_in[7];
    const float* b_fc    = (const float*)d_in[8];
    float* out = (float*)d_out;

    (void)in_sizes; (void)n_in; (void)out_size;

    // 0) bf16 hi/lo packing
    convert_x_kernel<<<MM, 192>>>(x);
    convert_w_kernel<<<G3, 192>>>(W_ih);

    // 1) Input projection via mma.sync (6 n-tiles x 1024 m-tiles, 256 thr)
    cudaFuncSetAttribute(gemm_mma_kernel,
                         cudaFuncAttributeMaxDynamicSharedMemorySize,
                         NSTG * STG_BYTES);
    dim3 ggrid(6, 1024);
    gemm_mma_kernel<<<ggrid, 256, NSTG * STG_BYTES>>>(b_ih);

    // 2) Scan (4-CTA clusters, register weights, local STS + 3x st.async)
    scan_kernel<<<128, 256>>>(rel_pos, alpha, W_hh, b_hh);

    // 3) Output FC
    fc_kernel<<<MM / 8, 256>>>(W_fc, b_fc, out);
}

// round 14
// speedup vs baseline: 1.1863x; 1.1422x over previous
#include <cuda_runtime.h>
#include <cuda_bf16.h>
#include <cuda_fp16.h>
#include <cooperative_groups.h>
#include <cstdint>

namespace cg = cooperative_groups;

// Problem constants
#define BB 128          // batch
#define SS 1024         // seq
#define II 768          // input dim
#define HH 256          // hidden
#define OO 6            // output
#define MM (BB * SS)    // 131072 rows
#define G3 (3 * HH)     // 768 gate rows

#define KH   1536       // packed K' = 2*768 (fp16: [xh | xl] / [Wh | Wh])
#define KHB  (KH * 2)   // 3072 bytes per packed row
#define NCHUNK (KH / 64)    // 24
#define NSTG 3
#define STG_BYTES 32768     // A 16KB + B 16KB

typedef unsigned long long ull;

// ---------------------------------------------------------------------------
// Scratch (device globals — allocation-free rule)
// ---------------------------------------------------------------------------
__device__ __align__(128) float g_xg[(size_t)MM * G3];        // [M, 768]
__device__ __align__(128) float g_hs[(size_t)MM * HH];        // [M, 256]
__device__ __align__(128) __half g_ax[(size_t)MM * KH];       // packed A' [xh|xl]
__device__ __align__(128) __half g_bx[(size_t)G3 * KH];       // packed B' [Wh|Wh]

// ---------------------------------------------------------------------------
// Generic-PTX helpers
// ---------------------------------------------------------------------------
__device__ __forceinline__ uint32_t smem_u32(const void* p) {
    uint32_t r;
    asm("{ .reg .u64 t; cvta.to.shared.u64 t, %1; cvt.u32.u64 %0, t; }"
        : "=r"(r) : "l"(p));
    return r;
}

__device__ __forceinline__ void cpa16(uint32_t saddr, const char* g) {
    asm volatile("cp.async.cg.shared.global [%0], [%1], 16;" :: "r"(saddr), "l"(g));
}

#define LDSM_X4(r, addr) \
    asm volatile("ldmatrix.sync.aligned.m8n8.x4.shared.b16 {%0,%1,%2,%3}, [%4];" \
                 : "=r"((r)[0]), "=r"((r)[1]), "=r"((r)[2]), "=r"((r)[3]) : "r"(addr))

#define MMA_16816_F16(d, a, b0, b1) \
    asm volatile("mma.sync.aligned.m16n8k16.row.col.f32.f16.f16.f32 " \
                 "{%0,%1,%2,%3}, {%4,%5,%6,%7}, {%8,%9}, {%0,%1,%2,%3};" \
                 : "+f"((d)[0]), "+f"((d)[1]), "+f"((d)[2]), "+f"((d)[3]) \
                 : "r"((a)[0]), "r"((a)[1]), "r"((a)[2]), "r"((a)[3]), \
                   "r"(b0), "r"(b1))

#define FMA2(acc, a, b) \
    asm("fma.rn.f32x2 %0, %1, %2, %0;" : "+l"(acc) : "l"(a), "l"(b))

#define MBAR_INIT(addr, cnt) \
    asm volatile("mbarrier.init.shared.b64 [%0], %1;" :: "r"(addr), "r"(cnt) : "memory")

#define MBAR_EXPECT_TX(addr, tx) \
    asm volatile("mbarrier.arrive.expect_tx.shared.b64 _, [%0], %1;" \
                 :: "r"(addr), "r"(tx) : "memory")

#define MBAR_ARRIVE(addr) \
    asm volatile("mbarrier.arrive.shared.b64 _, [%0];" :: "r"(addr) : "memory")

#define MBAR_WAIT_CL(addr, parity) do {                                        \
    uint32_t _m = (addr); uint32_t _p = (parity); uint32_t _d;                 \
    asm volatile("{\n\t.reg .pred p;\n\t"                                      \
        "mbarrier.try_wait.parity.acquire.cluster.shared::cta.b64 p, [%1], %2;\n\t" \
        "selp.b32 %0, 1, 0, p;\n\t}"                                           \
        : "=r"(_d) : "r"(_m), "r"(_p) : "memory");                             \
    if (!_d) {                                                                 \
        asm volatile("{\n\t.reg .pred P1;\n\t"                                 \
            "W_%=:\n\t"                                                        \
            "mbarrier.try_wait.parity.acquire.cluster.shared::cta.b64 P1, [%0], %1, 0x989680;\n\t" \
            "@P1 bra.uni D_%=;\n\t"                                            \
            "bra.uni W_%=;\n\t"                                                \
            "D_%=:\n\t}" :: "r"(_m), "r"(_p) : "memory");                      \
    }                                                                          \
} while (0)

#define ST_ASYNC_F32(raddr, val, rmbar) \
    asm volatile("st.async.shared::cluster.mbarrier::complete_tx::bytes.b32 [%0], %1, [%2];" \
                 :: "r"(raddr), "r"(__float_as_uint(val)), "r"(rmbar) : "memory")

#define MAPA_U32(out, local, rank) \
    asm("mapa.shared::cluster.u32 %0, %1, %2;" : "=r"(out) : "r"(local), "r"(rank))

// ===========================================================================
// Convert kernels: fp16 2-term split.
// A' = [xh (768) | xl (768)],  B' = [Wh (768) | Wh (768)]  (duplicated)
// ===========================================================================
__global__ __launch_bounds__(192) void convert_x_kernel(const float* __restrict__ x)
{
    const size_t row = blockIdx.x;
    const int t = threadIdx.x;
    float4 v = __ldg((const float4*)(x + row * II) + t);
    __half h0 = __float2half_rn(v.x);
    __half h1 = __float2half_rn(v.y);
    __half h2 = __float2half_rn(v.z);
    __half h3 = __float2half_rn(v.w);
    __half l0 = __float2half_rn(v.x - __half2float(h0));
    __half l1 = __float2half_rn(v.y - __half2float(h1));
    __half l2 = __float2half_rn(v.z - __half2float(h2));
    __half l3 = __float2half_rn(v.w - __half2float(h3));
    __half2 hp0 = __halves2half2(h0, h1);
    __half2 hp1 = __halves2half2(h2, h3);
    __half2 lp0 = __halves2half2(l0, l1);
    __half2 lp1 = __halves2half2(l2, l3);
    // row = 1536 half = 768 half2: hi at half2 [0,384), lo at [384,768)
    __half2* base = (__half2*)(g_ax + row * KH);
    base[t * 2]       = hp0;  base[t * 2 + 1]       = hp1;
    base[384 + t * 2] = lp0;  base[384 + t * 2 + 1] = lp1;
}

__global__ __launch_bounds__(192) void convert_w_kernel(const float* __restrict__ W)
{
    const size_t row = blockIdx.x;
    const int t = threadIdx.x;
    float4 v = __ldg((const float4*)(W + row * II) + t);
    __half h0 = __float2half_rn(v.x);
    __half h1 = __float2half_rn(v.y);
    __half h2 = __float2half_rn(v.z);
    __half h3 = __float2half_rn(v.w);
    __half2 hp0 = __halves2half2(h0, h1);
    __half2 hp1 = __halves2half2(h2, h3);
    // duplicate: chunk c<12 pairs xh*Wh; c>=12 pairs xl*Wh
    __half2* base = (__half2*)(g_bx + row * KH);
    base[t * 2]       = hp0;  base[t * 2 + 1]       = hp1;
    base[384 + t * 2] = hp0;  base[384 + t * 2 + 1] = hp1;
}

// ===========================================================================
// Kernel 1: xg = x @ W_ih^T + b_ih via mma.sync fp16 (f32 accum).
// R13 config: BN=128, 256 threads, 96KB smem -> 2 CTAs/SM, single-sync
// pipeline (wait_group 1 ; sync ; issue(c+2) ; compute(c)). K' = 1536.
// ===========================================================================
__global__ __launch_bounds__(256, 2) void gemm_mma_kernel(
    const float* __restrict__ bias)
{
    extern __shared__ __align__(1024) char dsm[];
    __shared__ float s_bias[128];

    const int tid  = threadIdx.x;
    const int lane = tid & 31;
    const int warp = tid >> 5;
    const int wm = warp >> 2;
    const int wn = warp & 3;
    const int n0 = blockIdx.x * 128;
    const size_t m0 = (size_t)blockIdx.y * 128;

    const uint32_t smem_base = smem_u32(dsm);

    if (tid < 128) s_bias[tid] = __ldg(bias + n0 + tid);

    const char* gA = (const char*)(g_ax) + m0 * KHB;
    const char* gB = (const char*)(g_bx) + (size_t)n0 * KHB;

    auto issue_loads = [&](int slot, int kbyte) {
        const uint32_t stgA = smem_base + slot * STG_BYTES;
        const uint32_t stgB = stgA + 16384;
#pragma unroll
        for (int i = 0; i < 4; i++) {
            int seg = tid + i * 256;
            int r = seg >> 3, c = seg & 7;
            uint32_t off = (uint32_t)(r * 128 + ((c ^ (r & 7)) << 4));
            const size_t goff = (size_t)r * KHB + kbyte + c * 16;
            cpa16(stgA + off, gA + goff);
            cpa16(stgB + off, gB + goff);
        }
    };

    const int lrow = (lane & 7) + ((lane >> 3) & 1) * 8;
    const int cp   = lane >> 4;
    const int arow = wm * 64 + lrow;
    const int brow = wn * 32 + lrow;

    float acc[4][4][4];
#pragma unroll
    for (int f = 0; f < 4; f++)
#pragma unroll
        for (int g = 0; g < 4; g++)
#pragma unroll
            for (int r = 0; r < 4; r++) acc[f][g][r] = 0.0f;

    issue_loads(0, 0);
    asm volatile("cp.async.commit_group;" ::: "memory");
    issue_loads(1, 128);
    asm volatile("cp.async.commit_group;" ::: "memory");

    for (int c = 0; c < NCHUNK; c++) {
        asm volatile("cp.async.wait_group 1;" ::: "memory");
        __syncthreads();

        const int lc = c + 2;
        if (lc < NCHUNK) issue_loads(lc % NSTG, lc * 128);
        asm volatile("cp.async.commit_group;" ::: "memory");

        const uint32_t stgA = smem_base + (c % NSTG) * STG_BYTES;
        const uint32_t stgB = stgA + 16384;

#pragma unroll
        for (int s = 0; s < 4; s++) {
            const int ach = ((2 * s + cp) ^ (arow & 7)) << 4;
            const int bch = ((2 * s + cp) ^ (brow & 7)) << 4;
            uint32_t a[4][4];
            uint32_t b[2][4];
#pragma unroll
            for (int f = 0; f < 4; f++)
                LDSM_X4(a[f], stgA + (uint32_t)((arow + f * 16) * 128 + ach));
#pragma unroll
            for (int g2 = 0; g2 < 2; g2++)
                LDSM_X4(b[g2], stgB + (uint32_t)((brow + g2 * 16) * 128 + bch));
#pragma unroll
            for (int f = 0; f < 4; f++) {
#pragma unroll
                for (int g = 0; g < 4; g++)
                    MMA_16816_F16(acc[f][g], a[f], b[g >> 1][g & 1], b[g >> 1][(g & 1) + 2]);
            }
        }
    }

    const int qrow = lane >> 2;
    const int qcol = (lane & 3) * 2;
#pragma unroll
    for (int f = 0; f < 4; f++) {
        const size_t gr = m0 + wm * 64 + f * 16 + qrow;
#pragma unroll
        for (int g = 0; g < 4; g++) {
            const int lc = wn * 32 + g * 8 + qcol;
            const float b0 = s_bias[lc], b1 = s_bias[lc + 1];
            float* p0 = g_xg + gr * G3 + n0 + lc;
            float* p1 = p0 + 8 * G3;
            *(float2*)p0 = make_float2(acc[f][g][0] + b0, acc[f][g][1] + b1);
            *(float2*)p1 = make_float2(acc[f][g][2] + b0, acc[f][g][3] + b1);
        }
    }
}

// ===========================================================================
// Kernel 2: GRU scan — EXACT R11/R13 (best known, ~2050 us):
// register weights, k-quarter split, local STS + 3x st.async exchange,
// decay exp precomputed in prefetch window, clamp-free gate math.
// ===========================================================================
#define HQ  68                // hbuf quarter stride (floats)
#define HBS (4 * HQ)          // per-batch stride = 272

__device__ __forceinline__ float fast_sig(float x) {
    return __fdividef(1.f, 1.f + __expf(-x));
}
__device__ __forceinline__ float fast_tanh(float x) {
    return 1.f - __fdividef(2.f, __expf(2.f * x) + 1.f);
}

__global__ void __cluster_dims__(4, 1, 1) __launch_bounds__(256, 1)
scan_kernel(const float* __restrict__ rel_pos, const float* __restrict__ alpha,
            const float* __restrict__ W_hh, const float* __restrict__ b_hh)
{
    __shared__ __align__(16) float hbuf[2 * 4 * HBS];   // [parity][b][4*68]
    __shared__ __align__(8) unsigned long long s_mbar[2];

    cg::cluster_group cluster = cg::this_cluster();
    const int crank = cluster.block_rank();     // 0..3
    const int cid   = blockIdx.x >> 2;          // 0..31
    const int tid   = threadIdx.x;
    const int u  = tid >> 2;                    // 0..63
    const int kq = tid & 3;                     // 0..3 (k-quarter, also batch)

    if (tid == 0) {
        MBAR_INIT(smem_u32(&s_mbar[0]), 256);
        MBAR_INIT(smem_u32(&s_mbar[1]), 256);
        asm volatile("fence.mbarrier_init.release.cluster;" ::: "memory");
    }
    cluster.sync();

    // ---- load this thread's weight slice into registers ----
    ull wr[32], wz[32], wn[32];
    {
        const ulonglong2* p0 = (const ulonglong2*)(W_hh +
            (size_t)(0 * 256 + crank * 64 + u) * HH + kq * 64);
        const ulonglong2* p1 = (const ulonglong2*)(W_hh +
            (size_t)(1 * 256 + crank * 64 + u) * HH + kq * 64);
        const ulonglong2* p2 = (const ulonglong2*)(W_hh +
            (size_t)(2 * 256 + crank * 64 + u) * HH + kq * 64);
#pragma unroll
        for (int i = 0; i < 16; i++) {
            ulonglong2 va = __ldg(p0 + i); wr[2 * i] = va.x; wr[2 * i + 1] = va.y;
            ulonglong2 vb = __ldg(p1 + i); wz[2 * i] = vb.x; wz[2 * i + 1] = vb.y;
            ulonglong2 vc = __ldg(p2 + i); wn[2 * i] = vc.x; wn[2 * i + 1] = vc.y;
        }
    }
    const float bias_r = __ldg(b_hh + 0 * 256 + crank * 64 + u);
    const float bias_z = __ldg(b_hh + 1 * 256 + crank * 64 + u);
    const float bias_n = __ldg(b_hh + 2 * 256 + crank * 64 + u);

    const int batch = cid * 4 + kq;             // this thread's gate batch
    const float a = fabsf(__ldg(alpha));

    const float* rp = rel_pos + (size_t)batch * SS;
    const float* xg_base = g_xg + ((size_t)batch * SS) * G3 + crank * 64 + u;
    float* hs_base = g_hs + ((size_t)batch * SS) * HH + crank * 64 + u;

    // own slot (local STS) + 3 remote targets (st.async)
    float* lown = &hbuf[kq * HBS + crank * HQ + u];
    uint32_t rhb[3], rmb[3];
    {
        uint32_t lslot = smem_u32(lown);
        uint32_t lmbar = smem_u32(&s_mbar[0]);
        int idx = 0;
#pragma unroll
        for (int r = 0; r < 4; r++) {
            if (r != crank) {
                MAPA_U32(rhb[idx], lslot, r);
                MAPA_U32(rmb[idx], lmbar, r);
                idx++;
            }
        }
    }
    const uint32_t lmb = smem_u32(&s_mbar[0]);

    // prefetch t = 0
    float rpt = __ldg(rp);
    float xr = __ldg(xg_base), xz = __ldg(xg_base + 256), xn = __ldg(xg_base + 512);
    float dec = __expf(-a * rpt);               // dt(0) = rp[0] - 0

    float h = 0.0f;

    for (int t = 0; t < SS; t++) {
        const uint32_t ph    = (uint32_t)(t & 1);
        const int      poff  = (int)ph * (4 * HBS);     // float offset
        const uint32_t poffB = ph * (uint32_t)(4 * HBS * 4);
        const uint32_t wp    = (uint32_t)((t >> 1) & 1);

        // decay (exp precomputed) + local STS + remote async broadcast
        float hd = h * dec;
        lown[poff] = hd;
        if (tid == 0) MBAR_EXPECT_TX(lmb + ph * 8, 3072u);
        else          MBAR_ARRIVE(lmb + ph * 8);
        ST_ASYNC_F32(rhb[0] + poffB, hd, rmb[0] + ph * 8);
        ST_ASYNC_F32(rhb[1] + poffB, hd, rmb[1] + ph * 8);
        ST_ASYNC_F32(rhb[2] + poffB, hd, rmb[2] + ph * 8);

        // prefetch next xg / rel_pos / decay while exchange is in flight
        const int tn = (t + 1 < SS) ? (t + 1) : (SS - 1);
        const float* xgn = xg_base + (size_t)tn * G3;
        float xr_n = __ldg(xgn), xz_n = __ldg(xgn + 256), xn_n = __ldg(xgn + 512);
        float rpt_n = __ldg(rp + tn);
        float dec_n = __expf(-a * (rpt_n - rpt));

        MBAR_WAIT_CL(lmb + ph * 8, wp);

        // k-quarter matvec for all 4 batches (weights in registers)
        float hr = 0.f, hz = 0.f, hnv = 0.f;
#pragma unroll
        for (int b = 0; b < 4; b++) {
            const ulonglong2* hb =
                (const ulonglong2*)(hbuf + poff + b * HBS + kq * HQ);
            ull ar = 0ull, az = 0ull, an = 0ull;
#pragma unroll
            for (int i = 0; i < 16; i++) {
                ulonglong2 hv = hb[i];
                FMA2(ar, wr[2 * i], hv.x); FMA2(ar, wr[2 * i + 1], hv.y);
                FMA2(az, wz[2 * i], hv.x); FMA2(az, wz[2 * i + 1], hv.y);
                FMA2(an, wn[2 * i], hv.x); FMA2(an, wn[2 * i + 1], hv.y);
            }
            float2 f;
            float pr, pz, pn;
            f = *(float2*)&ar; pr = f.x + f.y;
            f = *(float2*)&az; pz = f.x + f.y;
            f = *(float2*)&an; pn = f.x + f.y;
            pr += __shfl_xor_sync(0xFFFFFFFFu, pr, 1);
            pz += __shfl_xor_sync(0xFFFFFFFFu, pz, 1);
            pn += __shfl_xor_sync(0xFFFFFFFFu, pn, 1);
            pr += __shfl_xor_sync(0xFFFFFFFFu, pr, 2);
            pz += __shfl_xor_sync(0xFFFFFFFFu, pz, 2);
            pn += __shfl_xor_sync(0xFFFFFFFFu, pn, 2);
            if (kq == b) { hr = pr; hz = pz; hnv = pn; }
        }

        float r = fast_sig(xr + hr + bias_r);
        float z = fast_sig(xz + hz + bias_z);
        float n = fast_tanh(xn + (hnv + bias_n) * r);
        h = n + z * (hd - n);

        hs_base[(size_t)t * HH] = h;

        xr = xr_n; xz = xz_n; xn = xn_n; rpt = rpt_n; dec = dec_n;
    }

    // no CTA may exit while peers might still st.async into its smem
    cluster.sync();
}

// ===========================================================================
// Kernel 3: out = hs @ W_fc^T + b_fc.
// ===========================================================================
__global__ __launch_bounds__(256) void fc_kernel(
    const float* __restrict__ W_fc, const float* __restrict__ b_fc,
    float* __restrict__ out)
{
    __shared__ float Wsm[OO * HH];
    __shared__ float bsm[OO];
    const int tid = threadIdx.x;
    for (int i = tid; i < OO * HH; i += 256) Wsm[i] = W_fc[i];
    if (tid < OO) bsm[tid] = b_fc[tid];
    __syncthreads();

    const int warp = tid >> 5, lane = tid & 31;
    const size_t m = (size_t)blockIdx.x * 8 + warp;

    const float4* hp = (const float4*)(g_hs + m * HH + lane * 8);
    float4 hv0 = hp[0], hv1 = hp[1];

    float acc[OO];
#pragma unroll
    for (int o = 0; o < OO; o++) {
        const float* w = Wsm + o * HH + lane * 8;
        float4 w0 = *(const float4*)w;
        float4 w1 = *(const float4*)(w + 4);
        float s;
        s = hv0.x * w0.x;
        s = fmaf(hv0.y, w0.y, s);
        s = fmaf(hv0.z, w0.z, s);
        s = fmaf(hv0.w, w0.w, s);
        s = fmaf(hv1.x, w1.x, s);
        s = fmaf(hv1.y, w1.y, s);
        s = fmaf(hv1.z, w1.z, s);
        s = fmaf(hv1.w, w1.w, s);
        acc[o] = s;
    }
#pragma unroll
    for (int sft = 16; sft; sft >>= 1)
#pragma unroll
        for (int o = 0; o < OO; o++)
            acc[o] += __shfl_xor_sync(0xFFFFFFFFu, acc[o], sft);

    if (lane == 0) {
#pragma unroll
        for (int o = 0; o < OO; o++)
            out[m * OO + o] = acc[o] + bsm[o];
    }
}

// ===========================================================================
// Launch
// ===========================================================================
extern "C" void kernel_launch(void* const* d_in, const int* in_sizes, int n_in,
                              void* d_out, int out_size)
{
    const float* x       = (const float*)d_in[0];
    const float* rel_pos = (const float*)d_in[1];
    const float* alpha   = (const float*)d_in[2];
    const float* W_ih    = (const float*)d_in[3];
    const float* b_ih    = (const float*)d_in[4];
    const float* W_hh    = (const float*)d_in[5];
    const float* b_hh    = (const float*)d_in[6];
    const float* W_fc    = (const float*)d_in[7];
    const float* b_fc    = (const float*)d_in[8];
    float* out = (float*)d_out;

    (void)in_sizes; (void)n_in; (void)out_size;

    // 0) fp16 2-term packing (A' = [xh|xl], B' = [Wh|Wh])
    convert_x_kernel<<<MM, 192>>>(x);
    convert_w_kernel<<<G3, 192>>>(W_ih);

    // 1) Input projection via mma.sync fp16 (6 n-tiles x 1024 m-tiles)
    cudaFuncSetAttribute(gemm_mma_kernel,
                         cudaFuncAttributeMaxDynamicSharedMemorySize,
                         NSTG * STG_BYTES);
    dim3 ggrid(6, 1024);
    gemm_mma_kernel<<<ggrid, 256, NSTG * STG_BYTES>>>(b_ih);

    // 2) Scan (4-CTA clusters, register weights, local STS + 3x st.async)
    scan_kernel<<<128, 256>>>(rel_pos, alpha, W_hh, b_hh);

    // 3) Output FC
    fc_kernel<<<MM / 8, 256>>>(W_fc, b_fc, out);
}

// round 15
// speedup vs baseline: 1.3529x; 1.1404x over previous
#include <cuda_runtime.h>
#include <cuda_bf16.h>
#include <cuda_fp16.h>
#include <cooperative_groups.h>
#include <cstdint>

namespace cg = cooperative_groups;

// Problem constants
#define BB 128          // batch
#define SS 1024         // seq
#define II 768          // input dim
#define HH 256          // hidden
#define OO 6            // output
#define MM (BB * SS)    // 131072 rows
#define G3 (3 * HH)     // 768 gate rows

#define KH   768        // K (pure fp16, no split)
#define KHB  (KH * 2)   // 1536 bytes per row
#define NCHUNK (KH / 64)    // 12
#define NSTG 3
#define STG_BYTES 32768     // A 16KB + B 16KB

typedef unsigned long long ull;

// ---------------------------------------------------------------------------
// Scratch (device globals — allocation-free rule)
// ---------------------------------------------------------------------------
__device__ __align__(128) float g_xg[(size_t)MM * G3];        // [M, 768]
__device__ __align__(128) float g_hs[(size_t)MM * HH];        // [M, 256]
__device__ __align__(128) __half g_ax[(size_t)MM * KH];       // fp16(x)
__device__ __align__(128) __half g_bx[(size_t)G3 * KH];       // fp16(W_ih)

// ---------------------------------------------------------------------------
// Generic-PTX helpers
// ---------------------------------------------------------------------------
__device__ __forceinline__ uint32_t smem_u32(const void* p) {
    uint32_t r;
    asm("{ .reg .u64 t; cvta.to.shared.u64 t, %1; cvt.u32.u64 %0, t; }"
        : "=r"(r) : "l"(p));
    return r;
}

__device__ __forceinline__ void cpa16(uint32_t saddr, const char* g) {
    asm volatile("cp.async.cg.shared.global [%0], [%1], 16;" :: "r"(saddr), "l"(g));
}

#define LDSM_X4(r, addr) \
    asm volatile("ldmatrix.sync.aligned.m8n8.x4.shared.b16 {%0,%1,%2,%3}, [%4];" \
                 : "=r"((r)[0]), "=r"((r)[1]), "=r"((r)[2]), "=r"((r)[3]) : "r"(addr))

#define MMA_16816_F16(d, a, b0, b1) \
    asm volatile("mma.sync.aligned.m16n8k16.row.col.f32.f16.f16.f32 " \
                 "{%0,%1,%2,%3}, {%4,%5,%6,%7}, {%8,%9}, {%0,%1,%2,%3};" \
                 : "+f"((d)[0]), "+f"((d)[1]), "+f"((d)[2]), "+f"((d)[3]) \
                 : "r"((a)[0]), "r"((a)[1]), "r"((a)[2]), "r"((a)[3]), \
                   "r"(b0), "r"(b1))

#define FMA2(acc, a, b) \
    asm("fma.rn.f32x2 %0, %1, %2, %0;" : "+l"(acc) : "l"(a), "l"(b))

#define MBAR_INIT(addr, cnt) \
    asm volatile("mbarrier.init.shared.b64 [%0], %1;" :: "r"(addr), "r"(cnt) : "memory")

#define MBAR_EXPECT_TX(addr, tx) \
    asm volatile("mbarrier.arrive.expect_tx.shared.b64 _, [%0], %1;" \
                 :: "r"(addr), "r"(tx) : "memory")

#define MBAR_ARRIVE(addr) \
    asm volatile("mbarrier.arrive.shared.b64 _, [%0];" :: "r"(addr) : "memory")

#define MBAR_WAIT_CL(addr, parity) do {                                        \
    uint32_t _m = (addr); uint32_t _p = (parity); uint32_t _d;                 \
    asm volatile("{\n\t.reg .pred p;\n\t"                                      \
        "mbarrier.try_wait.parity.acquire.cluster.shared::cta.b64 p, [%1], %2;\n\t" \
        "selp.b32 %0, 1, 0, p;\n\t}"                                           \
        : "=r"(_d) : "r"(_m), "r"(_p) : "memory");                             \
    if (!_d) {                                                                 \
        asm volatile("{\n\t.reg .pred P1;\n\t"                                 \
            "W_%=:\n\t"                                                        \
            "mbarrier.try_wait.parity.acquire.cluster.shared::cta.b64 P1, [%0], %1, 0x989680;\n\t" \
            "@P1 bra.uni D_%=;\n\t"                                            \
            "bra.uni W_%=;\n\t"                                                \
            "D_%=:\n\t}" :: "r"(_m), "r"(_p) : "memory");                      \
    }                                                                          \
} while (0)

#define ST_ASYNC_F32(raddr, val, rmbar) \
    asm volatile("st.async.shared::cluster.mbarrier::complete_tx::bytes.b32 [%0], %1, [%2];" \
                 :: "r"(raddr), "r"(__float_as_uint(val)), "r"(rmbar) : "memory")

#define MAPA_U32(out, local, rank) \
    asm("mapa.shared::cluster.u32 %0, %1, %2;" : "=r"(out) : "r"(local), "r"(rank))

// ===========================================================================
// Convert kernels: straight fp16 casts (no split).
// ===========================================================================
__global__ __launch_bounds__(192) void convert_x_kernel(const float* __restrict__ x)
{
    const size_t row = blockIdx.x;
    const int t = threadIdx.x;
    float4 v = __ldg((const float4*)(x + row * II) + t);
    __half2 hp0 = __halves2half2(__float2half_rn(v.x), __float2half_rn(v.y));
    __half2 hp1 = __halves2half2(__float2half_rn(v.z), __float2half_rn(v.w));
    __half2* base = (__half2*)(g_ax + row * KH);
    base[t * 2]     = hp0;
    base[t * 2 + 1] = hp1;
}

__global__ __launch_bounds__(192) void convert_w_kernel(const float* __restrict__ W)
{
    const size_t row = blockIdx.x;
    const int t = threadIdx.x;
    float4 v = __ldg((const float4*)(W + row * II) + t);
    __half2 hp0 = __halves2half2(__float2half_rn(v.x), __float2half_rn(v.y));
    __half2 hp1 = __halves2half2(__float2half_rn(v.z), __float2half_rn(v.w));
    __half2* base = (__half2*)(g_bx + row * KH);
    base[t * 2]     = hp0;
    base[t * 2 + 1] = hp1;
}

// ===========================================================================
// Kernel 1: xg = x @ W_ih^T + b_ih via mma.sync fp16 (f32 accum), K=768.
// R13 config: BN=128, 256 threads, 96KB smem -> 2 CTAs/SM, single-sync
// pipeline (wait_group 1 ; sync ; issue(c+2) ; compute(c)).
// ===========================================================================
__global__ __launch_bounds__(256, 2) void gemm_mma_kernel(
    const float* __restrict__ bias)
{
    extern __shared__ __align__(1024) char dsm[];
    __shared__ float s_bias[128];

    const int tid  = threadIdx.x;
    const int lane = tid & 31;
    const int warp = tid >> 5;
    const int wm = warp >> 2;
    const int wn = warp & 3;
    const int n0 = blockIdx.x * 128;
    const size_t m0 = (size_t)blockIdx.y * 128;

    const uint32_t smem_base = smem_u32(dsm);

    if (tid < 128) s_bias[tid] = __ldg(bias + n0 + tid);

    const char* gA = (const char*)(g_ax) + m0 * KHB;
    const char* gB = (const char*)(g_bx) + (size_t)n0 * KHB;

    auto issue_loads = [&](int slot, int kbyte) {
        const uint32_t stgA = smem_base + slot * STG_BYTES;
        const uint32_t stgB = stgA + 16384;
#pragma unroll
        for (int i = 0; i < 4; i++) {
            int seg = tid + i * 256;
            int r = seg >> 3, c = seg & 7;
            uint32_t off = (uint32_t)(r * 128 + ((c ^ (r & 7)) << 4));
            const size_t goff = (size_t)r * KHB + kbyte + c * 16;
            cpa16(stgA + off, gA + goff);
            cpa16(stgB + off, gB + goff);
        }
    };

    const int lrow = (lane & 7) + ((lane >> 3) & 1) * 8;
    const int cp   = lane >> 4;
    const int arow = wm * 64 + lrow;
    const int brow = wn * 32 + lrow;

    float acc[4][4][4];
#pragma unroll
    for (int f = 0; f < 4; f++)
#pragma unroll
        for (int g = 0; g < 4; g++)
#pragma unroll
            for (int r = 0; r < 4; r++) acc[f][g][r] = 0.0f;

    issue_loads(0, 0);
    asm volatile("cp.async.commit_group;" ::: "memory");
    issue_loads(1, 128);
    asm volatile("cp.async.commit_group;" ::: "memory");

    for (int c = 0; c < NCHUNK; c++) {
        asm volatile("cp.async.wait_group 1;" ::: "memory");
        __syncthreads();

        const int lc = c + 2;
        if (lc < NCHUNK) issue_loads(lc % NSTG, lc * 128);
        asm volatile("cp.async.commit_group;" ::: "memory");

        const uint32_t stgA = smem_base + (c % NSTG) * STG_BYTES;
        const uint32_t stgB = stgA + 16384;

#pragma unroll
        for (int s = 0; s < 4; s++) {
            const int ach = ((2 * s + cp) ^ (arow & 7)) << 4;
            const int bch = ((2 * s + cp) ^ (brow & 7)) << 4;
            uint32_t a[4][4];
            uint32_t b[2][4];
#pragma unroll
            for (int f = 0; f < 4; f++)
                LDSM_X4(a[f], stgA + (uint32_t)((arow + f * 16) * 128 + ach));
#pragma unroll
            for (int g2 = 0; g2 < 2; g2++)
                LDSM_X4(b[g2], stgB + (uint32_t)((brow + g2 * 16) * 128 + bch));
#pragma unroll
            for (int f = 0; f < 4; f++) {
#pragma unroll
                for (int g = 0; g < 4; g++)
                    MMA_16816_F16(acc[f][g], a[f], b[g >> 1][g & 1], b[g >> 1][(g & 1) + 2]);
            }
        }
    }

    const int qrow = lane >> 2;
    const int qcol = (lane & 3) * 2;
#pragma unroll
    for (int f = 0; f < 4; f++) {
        const size_t gr = m0 + wm * 64 + f * 16 + qrow;
#pragma unroll
        for (int g = 0; g < 4; g++) {
            const int lc = wn * 32 + g * 8 + qcol;
            const float b0 = s_bias[lc], b1 = s_bias[lc + 1];
            float* p0 = g_xg + gr * G3 + n0 + lc;
            float* p1 = p0 + 8 * G3;
            *(float2*)p0 = make_float2(acc[f][g][0] + b0, acc[f][g][1] + b1);
            *(float2*)p1 = make_float2(acc[f][g][2] + b0, acc[f][g][3] + b1);
        }
    }
}

// ===========================================================================
// Kernel 2: GRU scan — EXACT R11/R13/R14 (best known, ~2030 us):
// register weights, k-quarter split, local STS + 3x st.async exchange,
// decay exp precomputed in prefetch window, clamp-free gate math.
// ===========================================================================
#define HQ  68                // hbuf quarter stride (floats)
#define HBS (4 * HQ)          // per-batch stride = 272

__device__ __forceinline__ float fast_sig(float x) {
    return __fdividef(1.f, 1.f + __expf(-x));
}
__device__ __forceinline__ float fast_tanh(float x) {
    return 1.f - __fdividef(2.f, __expf(2.f * x) + 1.f);
}

__global__ void __cluster_dims__(4, 1, 1) __launch_bounds__(256, 1)
scan_kernel(const float* __restrict__ rel_pos, const float* __restrict__ alpha,
            const float* __restrict__ W_hh, const float* __restrict__ b_hh)
{
    __shared__ __align__(16) float hbuf[2 * 4 * HBS];   // [parity][b][4*68]
    __shared__ __align__(8) unsigned long long s_mbar[2];

    cg::cluster_group cluster = cg::this_cluster();
    const int crank = cluster.block_rank();     // 0..3
    const int cid   = blockIdx.x >> 2;          // 0..31
    const int tid   = threadIdx.x;
    const int u  = tid >> 2;                    // 0..63
    const int kq = tid & 3;                     // 0..3 (k-quarter, also batch)

    if (tid == 0) {
        MBAR_INIT(smem_u32(&s_mbar[0]), 256);
        MBAR_INIT(smem_u32(&s_mbar[1]), 256);
        asm volatile("fence.mbarrier_init.release.cluster;" ::: "memory");
    }
    cluster.sync();

    // ---- load this thread's weight slice into registers ----
    ull wr[32], wz[32], wn[32];
    {
        const ulonglong2* p0 = (const ulonglong2*)(W_hh +
            (size_t)(0 * 256 + crank * 64 + u) * HH + kq * 64);
        const ulonglong2* p1 = (const ulonglong2*)(W_hh +
            (size_t)(1 * 256 + crank * 64 + u) * HH + kq * 64);
        const ulonglong2* p2 = (const ulonglong2*)(W_hh +
            (size_t)(2 * 256 + crank * 64 + u) * HH + kq * 64);
#pragma unroll
        for (int i = 0; i < 16; i++) {
            ulonglong2 va = __ldg(p0 + i); wr[2 * i] = va.x; wr[2 * i + 1] = va.y;
            ulonglong2 vb = __ldg(p1 + i); wz[2 * i] = vb.x; wz[2 * i + 1] = vb.y;
            ulonglong2 vc = __ldg(p2 + i); wn[2 * i] = vc.x; wn[2 * i + 1] = vc.y;
        }
    }
    const float bias_r = __ldg(b_hh + 0 * 256 + crank * 64 + u);
    const float bias_z = __ldg(b_hh + 1 * 256 + crank * 64 + u);
    const float bias_n = __ldg(b_hh + 2 * 256 + crank * 64 + u);

    const int batch = cid * 4 + kq;             // this thread's gate batch
    const float a = fabsf(__ldg(alpha));

    const float* rp = rel_pos + (size_t)batch * SS;
    const float* xg_base = g_xg + ((size_t)batch * SS) * G3 + crank * 64 + u;
    float* hs_base = g_hs + ((size_t)batch * SS) * HH + crank * 64 + u;

    // own slot (local STS) + 3 remote targets (st.async)
    float* lown = &hbuf[kq * HBS + crank * HQ + u];
    uint32_t rhb[3], rmb[3];
    {
        uint32_t lslot = smem_u32(lown);
        uint32_t lmbar = smem_u32(&s_mbar[0]);
        int idx = 0;
#pragma unroll
        for (int r = 0; r < 4; r++) {
            if (r != crank) {
                MAPA_U32(rhb[idx], lslot, r);
                MAPA_U32(rmb[idx], lmbar, r);
                idx++;
            }
        }
    }
    const uint32_t lmb = smem_u32(&s_mbar[0]);

    // prefetch t = 0
    float rpt = __ldg(rp);
    float xr = __ldg(xg_base), xz = __ldg(xg_base + 256), xn = __ldg(xg_base + 512);
    float dec = __expf(-a * rpt);               // dt(0) = rp[0] - 0

    float h = 0.0f;

    for (int t = 0; t < SS; t++) {
        const uint32_t ph    = (uint32_t)(t & 1);
        const int      poff  = (int)ph * (4 * HBS);     // float offset
        const uint32_t poffB = ph * (uint32_t)(4 * HBS * 4);
        const uint32_t wp    = (uint32_t)((t >> 1) & 1);

        // decay (exp precomputed) + local STS + remote async broadcast
        float hd = h * dec;
        lown[poff] = hd;
        if (tid == 0) MBAR_EXPECT_TX(lmb + ph * 8, 3072u);
        else          MBAR_ARRIVE(lmb + ph * 8);
        ST_ASYNC_F32(rhb[0] + poffB, hd, rmb[0] + ph * 8);
        ST_ASYNC_F32(rhb[1] + poffB, hd, rmb[1] + ph * 8);
        ST_ASYNC_F32(rhb[2] + poffB, hd, rmb[2] + ph * 8);

        // prefetch next xg / rel_pos / decay while exchange is in flight
        const int tn = (t + 1 < SS) ? (t + 1) : (SS - 1);
        const float* xgn = xg_base + (size_t)tn * G3;
        float xr_n = __ldg(xgn), xz_n = __ldg(xgn + 256), xn_n = __ldg(xgn + 512);
        float rpt_n = __ldg(rp + tn);
        float dec_n = __expf(-a * (rpt_n - rpt));

        MBAR_WAIT_CL(lmb + ph * 8, wp);

        // k-quarter matvec for all 4 batches (weights in registers)
        float hr = 0.f, hz = 0.f, hnv = 0.f;
#pragma unroll
        for (int b = 0; b < 4; b++) {
            const ulonglong2* hb =
                (const ulonglong2*)(hbuf + poff + b * HBS + kq * HQ);
            ull ar = 0ull, az = 0ull, an = 0ull;
#pragma unroll
            for (int i = 0; i < 16; i++) {
                ulonglong2 hv = hb[i];
                FMA2(ar, wr[2 * i], hv.x); FMA2(ar, wr[2 * i + 1], hv.y);
                FMA2(az, wz[2 * i], hv.x); FMA2(az, wz[2 * i + 1], hv.y);
                FMA2(an, wn[2 * i], hv.x); FMA2(an, wn[2 * i + 1], hv.y);
            }
            float2 f;
            float pr, pz, pn;
            f = *(float2*)&ar; pr = f.x + f.y;
            f = *(float2*)&az; pz = f.x + f.y;
            f = *(float2*)&an; pn = f.x + f.y;
            pr += __shfl_xor_sync(0xFFFFFFFFu, pr, 1);
            pz += __shfl_xor_sync(0xFFFFFFFFu, pz, 1);
            pn += __shfl_xor_sync(0xFFFFFFFFu, pn, 1);
            pr += __shfl_xor_sync(0xFFFFFFFFu, pr, 2);
            pz += __shfl_xor_sync(0xFFFFFFFFu, pz, 2);
            pn += __shfl_xor_sync(0xFFFFFFFFu, pn, 2);
            if (kq == b) { hr = pr; hz = pz; hnv = pn; }
        }

        float r = fast_sig(xr + hr + bias_r);
        float z = fast_sig(xz + hz + bias_z);
        float n = fast_tanh(xn + (hnv + bias_n) * r);
        h = n + z * (hd - n);

        hs_base[(size_t)t * HH] = h;

        xr = xr_n; xz = xz_n; xn = xn_n; rpt = rpt_n; dec = dec_n;
    }

    // no CTA may exit while peers might still st.async into its smem
    cluster.sync();
}

// ===========================================================================
// Kernel 3: out = hs @ W_fc^T + b_fc.
// ===========================================================================
__global__ __launch_bounds__(256) void fc_kernel(
    const float* __restrict__ W_fc, const float* __restrict__ b_fc,
    float* __restrict__ out)
{
    __shared__ float Wsm[OO * HH];
    __shared__ float bsm[OO];
    const int tid = threadIdx.x;
    for (int i = tid; i < OO * HH; i += 256) Wsm[i] = W_fc[i];
    if (tid < OO) bsm[tid] = b_fc[tid];
    __syncthreads();

    const int warp = tid >> 5, lane = tid & 31;
    const size_t m = (size_t)blockIdx.x * 8 + warp;

    const float4* hp = (const float4*)(g_hs + m * HH + lane * 8);
    float4 hv0 = hp[0], hv1 = hp[1];

    float acc[OO];
#pragma unroll
    for (int o = 0; o < OO; o++) {
        const float* w = Wsm + o * HH + lane * 8;
        float4 w0 = *(const float4*)w;
        float4 w1 = *(const float4*)(w + 4);
        float s;
        s = hv0.x * w0.x;
        s = fmaf(hv0.y, w0.y, s);
        s = fmaf(hv0.z, w0.z, s);
        s = fmaf(hv0.w, w0.w, s);
        s = fmaf(hv1.x, w1.x, s);
        s = fmaf(hv1.y, w1.y, s);
        s = fmaf(hv1.z, w1.z, s);
        s = fmaf(hv1.w, w1.w, s);
        acc[o] = s;
    }
#pragma unroll
    for (int sft = 16; sft; sft >>= 1)
#pragma unroll
        for (int o = 0; o < OO; o++)
            acc[o] += __shfl_xor_sync(0xFFFFFFFFu, acc[o], sft);

    if (lane == 0) {
#pragma unroll
        for (int o = 0; o < OO; o++)
            out[m * OO + o] = acc[o] + bsm[o];
    }
}

// ===========================================================================
// Launch
// ===========================================================================
extern "C" void kernel_launch(void* const* d_in, const int* in_sizes, int n_in,
                              void* d_out, int out_size)
{
    const float* x       = (const float*)d_in[0];
    const float* rel_pos = (const float*)d_in[1];
    const float* alpha   = (const float*)d_in[2];
    const float* W_ih    = (const float*)d_in[3];
    const float* b_ih    = (const float*)d_in[4];
    const float* W_hh    = (const float*)d_in[5];
    const float* b_hh    = (const float*)d_in[6];
    const float* W_fc    = (const float*)d_in[7];
    const float* b_fc    = (const float*)d_in[8];
    float* out = (float*)d_out;

    (void)in_sizes; (void)n_in; (void)out_size;

    // 0) fp16 casts (no split)
    convert_x_kernel<<<MM, 192>>>(x);
    convert_w_kernel<<<G3, 192>>>(W_ih);

    // 1) Input projection via mma.sync fp16, K=768
    cudaFuncSetAttribute(gemm_mma_kernel,
                         cudaFuncAttributeMaxDynamicSharedMemorySize,
                         NSTG * STG_BYTES);
    dim3 ggrid(6, 1024);
    gemm_mma_kernel<<<ggrid, 256, NSTG * STG_BYTES>>>(b_ih);

    // 2) Scan (4-CTA clusters, register weights, local STS + 3x st.async)
    scan_kernel<<<128, 256>>>(rel_pos, alpha, W_hh, b_hh);

    // 3) Output FC
    fc_kernel<<<MM / 8, 256>>>(W_fc, b_fc, out);
}

// round 16
// speedup vs baseline: 1.8379x; 1.3585x over previous
#include <cuda_runtime.h>
#include <cuda_bf16.h>
#include <cuda_fp16.h>
#include <cooperative_groups.h>
#include <cstdint>

namespace cg = cooperative_groups;

// Problem constants
#define BB 128          // batch
#define SS 1024         // seq
#define II 768          // input dim
#define HH 256          // hidden
#define OO 6            // output
#define MM (BB * SS)    // 131072 rows
#define G3 (3 * HH)     // 768 gate rows

#define KH   768        // K (pure fp16, no split)
#define KHB  (KH * 2)   // 1536 bytes per row
#define NCHUNK (KH / 64)    // 12
#define NSTG 3
#define STG_BYTES 32768     // A 16KB + B 16KB

typedef unsigned long long ull;

// ---------------------------------------------------------------------------
// Scratch (device globals — allocation-free rule)
// ---------------------------------------------------------------------------
__device__ __align__(128) float g_xg[(size_t)MM * G3];        // [M, 768]
__device__ __align__(128) float g_hs[(size_t)MM * HH];        // [M, 256]
__device__ __align__(128) __half g_ax[(size_t)MM * KH];       // fp16(x)
__device__ __align__(128) __half g_bx[(size_t)G3 * KH];       // fp16(W_ih)

// ---------------------------------------------------------------------------
// Generic-PTX helpers
// ---------------------------------------------------------------------------
__device__ __forceinline__ uint32_t smem_u32(const void* p) {
    uint32_t r;
    asm("{ .reg .u64 t; cvta.to.shared.u64 t, %1; cvt.u32.u64 %0, t; }"
        : "=r"(r) : "l"(p));
    return r;
}

__device__ __forceinline__ void cpa16(uint32_t saddr, const char* g) {
    asm volatile("cp.async.cg.shared.global [%0], [%1], 16;" :: "r"(saddr), "l"(g));
}

#define LDSM_X4(r, addr) \
    asm volatile("ldmatrix.sync.aligned.m8n8.x4.shared.b16 {%0,%1,%2,%3}, [%4];" \
                 : "=r"((r)[0]), "=r"((r)[1]), "=r"((r)[2]), "=r"((r)[3]) : "r"(addr))

#define MMA_16816_F16(d, a, b0, b1) \
    asm volatile("mma.sync.aligned.m16n8k16.row.col.f32.f16.f16.f32 " \
                 "{%0,%1,%2,%3}, {%4,%5,%6,%7}, {%8,%9}, {%0,%1,%2,%3};" \
                 : "+f"((d)[0]), "+f"((d)[1]), "+f"((d)[2]), "+f"((d)[3]) \
                 : "r"((a)[0]), "r"((a)[1]), "r"((a)[2]), "r"((a)[3]), \
                   "r"(b0), "r"(b1))

#define MBAR_INIT(addr, cnt) \
    asm volatile("mbarrier.init.shared.b64 [%0], %1;" :: "r"(addr), "r"(cnt) : "memory")

#define MBAR_EXPECT_TX(addr, tx) \
    asm volatile("mbarrier.arrive.expect_tx.shared.b64 _, [%0], %1;" \
                 :: "r"(addr), "r"(tx) : "memory")

#define MBAR_ARRIVE(addr) \
    asm volatile("mbarrier.arrive.shared.b64 _, [%0];" :: "r"(addr) : "memory")

#define MBAR_WAIT_CL(addr, parity) do {                                        \
    uint32_t _m = (addr); uint32_t _p = (parity); uint32_t _d;                 \
    asm volatile("{\n\t.reg .pred p;\n\t"                                      \
        "mbarrier.try_wait.parity.acquire.cluster.shared::cta.b64 p, [%1], %2;\n\t" \
        "selp.b32 %0, 1, 0, p;\n\t}"                                           \
        : "=r"(_d) : "r"(_m), "r"(_p) : "memory");                             \
    if (!_d) {                                                                 \
        asm volatile("{\n\t.reg .pred P1;\n\t"                                 \
            "W_%=:\n\t"                                                        \
            "mbarrier.try_wait.parity.acquire.cluster.shared::cta.b64 P1, [%0], %1, 0x989680;\n\t" \
            "@P1 bra.uni D_%=;\n\t"                                            \
            "bra.uni W_%=;\n\t"                                                \
            "D_%=:\n\t}" :: "r"(_m), "r"(_p) : "memory");                      \
    }                                                                          \
} while (0)

#define ST_ASYNC_F32(raddr, val, rmbar) \
    asm volatile("st.async.shared::cluster.mbarrier::complete_tx::bytes.b32 [%0], %1, [%2];" \
                 :: "r"(raddr), "r"(__float_as_uint(val)), "r"(rmbar) : "memory")

#define MAPA_U32(out, local, rank) \
    asm("mapa.shared::cluster.u32 %0, %1, %2;" : "=r"(out) : "r"(local), "r"(rank))

// ===========================================================================
// Convert kernels: straight fp16 casts (no split).
// ===========================================================================
__global__ __launch_bounds__(192) void convert_x_kernel(const float* __restrict__ x)
{
    const size_t row = blockIdx.x;
    const int t = threadIdx.x;
    float4 v = __ldg((const float4*)(x + row * II) + t);
    __half2 hp0 = __halves2half2(__float2half_rn(v.x), __float2half_rn(v.y));
    __half2 hp1 = __halves2half2(__float2half_rn(v.z), __float2half_rn(v.w));
    __half2* base = (__half2*)(g_ax + row * KH);
    base[t * 2]     = hp0;
    base[t * 2 + 1] = hp1;
}

__global__ __launch_bounds__(192) void convert_w_kernel(const float* __restrict__ W)
{
    const size_t row = blockIdx.x;
    const int t = threadIdx.x;
    float4 v = __ldg((const float4*)(W + row * II) + t);
    __half2 hp0 = __halves2half2(__float2half_rn(v.x), __float2half_rn(v.y));
    __half2 hp1 = __halves2half2(__float2half_rn(v.z), __float2half_rn(v.w));
    __half2* base = (__half2*)(g_bx + row * KH);
    base[t * 2]     = hp0;
    base[t * 2 + 1] = hp1;
}

// ===========================================================================
// Kernel 1: xg = x @ W_ih^T + b_ih via mma.sync fp16 (f32 accum), K=768.
// (exact R15 — known good)
// ===========================================================================
__global__ __launch_bounds__(256, 2) void gemm_mma_kernel(
    const float* __restrict__ bias)
{
    extern __shared__ __align__(1024) char dsm[];
    __shared__ float s_bias[128];

    const int tid  = threadIdx.x;
    const int lane = tid & 31;
    const int warp = tid >> 5;
    const int wm = warp >> 2;
    const int wn = warp & 3;
    const int n0 = blockIdx.x * 128;
    const size_t m0 = (size_t)blockIdx.y * 128;

    const uint32_t smem_base = smem_u32(dsm);

    if (tid < 128) s_bias[tid] = __ldg(bias + n0 + tid);

    const char* gA = (const char*)(g_ax) + m0 * KHB;
    const char* gB = (const char*)(g_bx) + (size_t)n0 * KHB;

    auto issue_loads = [&](int slot, int kbyte) {
        const uint32_t stgA = smem_base + slot * STG_BYTES;
        const uint32_t stgB = stgA + 16384;
#pragma unroll
        for (int i = 0; i < 4; i++) {
            int seg = tid + i * 256;
            int r = seg >> 3, c = seg & 7;
            uint32_t off = (uint32_t)(r * 128 + ((c ^ (r & 7)) << 4));
            const size_t goff = (size_t)r * KHB + kbyte + c * 16;
            cpa16(stgA + off, gA + goff);
            cpa16(stgB + off, gB + goff);
        }
    };

    const int lrow = (lane & 7) + ((lane >> 3) & 1) * 8;
    const int cp   = lane >> 4;
    const int arow = wm * 64 + lrow;
    const int brow = wn * 32 + lrow;

    float acc[4][4][4];
#pragma unroll
    for (int f = 0; f < 4; f++)
#pragma unroll
        for (int g = 0; g < 4; g++)
#pragma unroll
            for (int r = 0; r < 4; r++) acc[f][g][r] = 0.0f;

    issue_loads(0, 0);
    asm volatile("cp.async.commit_group;" ::: "memory");
    issue_loads(1, 128);
    asm volatile("cp.async.commit_group;" ::: "memory");

    for (int c = 0; c < NCHUNK; c++) {
        asm volatile("cp.async.wait_group 1;" ::: "memory");
        __syncthreads();

        const int lc = c + 2;
        if (lc < NCHUNK) issue_loads(lc % NSTG, lc * 128);
        asm volatile("cp.async.commit_group;" ::: "memory");

        const uint32_t stgA = smem_base + (c % NSTG) * STG_BYTES;
        const uint32_t stgB = stgA + 16384;

#pragma unroll
        for (int s = 0; s < 4; s++) {
            const int ach = ((2 * s + cp) ^ (arow & 7)) << 4;
            const int bch = ((2 * s + cp) ^ (brow & 7)) << 4;
            uint32_t a[4][4];
            uint32_t b[2][4];
#pragma unroll
            for (int f = 0; f < 4; f++)
                LDSM_X4(a[f], stgA + (uint32_t)((arow + f * 16) * 128 + ach));
#pragma unroll
            for (int g2 = 0; g2 < 2; g2++)
                LDSM_X4(b[g2], stgB + (uint32_t)((brow + g2 * 16) * 128 + bch));
#pragma unroll
            for (int f = 0; f < 4; f++) {
#pragma unroll
                for (int g = 0; g < 4; g++)
                    MMA_16816_F16(acc[f][g], a[f], b[g >> 1][g & 1], b[g >> 1][(g & 1) + 2]);
            }
        }
    }

    const int qrow = lane >> 2;
    const int qcol = (lane & 3) * 2;
#pragma unroll
    for (int f = 0; f < 4; f++) {
        const size_t gr = m0 + wm * 64 + f * 16 + qrow;
#pragma unroll
        for (int g = 0; g < 4; g++) {
            const int lc = wn * 32 + g * 8 + qcol;
            const float b0 = s_bias[lc], b1 = s_bias[lc + 1];
            float* p0 = g_xg + gr * G3 + n0 + lc;
            float* p1 = p0 + 8 * G3;
            *(float2*)p0 = make_float2(acc[f][g][0] + b0, acc[f][g][1] + b1);
            *(float2*)p1 = make_float2(acc[f][g][2] + b0, acc[f][g][3] + b1);
        }
    }
}

// ===========================================================================
// Kernel 2: GRU scan — tensor-core matvec.
// 4-CTA cluster = 4 batches; CTA rank owns 192 local gate rows
// (rho = g*64 + u  ->  global row g*256 + crank*64 + u), K = 256 full.
// Per step: hd exchange (fp32 st.async, unchanged) -> cvt h to fp16 A-smem
// [16 rows x 256, pitch 528B, rows 4-15 zero] -> ldmatrix + mma.m16n8k16
// (W_hh fragments resident in 96 regs) -> hg rows 0-3 to smem -> gate math.
// ===========================================================================
#define HQ  68                // hbuf quarter stride (floats)
#define HBS (4 * HQ)          // per-batch stride = 272
#define APITCH 528            // A-smem row pitch (bytes) -> conflict-free ldsm

__device__ __forceinline__ float fast_sig(float x) {
    return __fdividef(1.f, 1.f + __expf(-x));
}
__device__ __forceinline__ float fast_tanh(float x) {
    return 1.f - __fdividef(2.f, __expf(2.f * x) + 1.f);
}

__global__ void __cluster_dims__(4, 1, 1) __launch_bounds__(256, 1)
scan_kernel(const float* __restrict__ rel_pos, const float* __restrict__ alpha,
            const float* __restrict__ W_hh, const float* __restrict__ b_hh)
{
    __shared__ __align__(16) __half a_sm[16 * (APITCH / 2)];   // 8448 B
    __shared__ __align__(16) float hbuf[2 * 4 * HBS];          // fp32 exchange
    __shared__ __align__(16) float hg_sm[4 * 200];             // [batch][192+pad]
    __shared__ __align__(8) unsigned long long s_mbar[2];

    cg::cluster_group cluster = cg::this_cluster();
    const int crank = cluster.block_rank();     // 0..3
    const int cid   = blockIdx.x >> 2;          // 0..31
    const int tid   = threadIdx.x;
    const int lane  = tid & 31;
    const int warp  = tid >> 5;                 // 0..7
    const int u  = tid >> 2;                    // 0..63
    const int kq = tid & 3;                     // batch within cluster

    if (tid == 0) {
        MBAR_INIT(smem_u32(&s_mbar[0]), 256);
        MBAR_INIT(smem_u32(&s_mbar[1]), 256);
        asm volatile("fence.mbarrier_init.release.cluster;" ::: "memory");
    }
    // zero all of A-smem (rows 4-15 stay zero forever)
    for (int i = tid; i < 16 * (APITCH / 2); i += 256)
        a_sm[i] = __ushort_as_half((unsigned short)0);
    cluster.sync();

    // ---- W_hh B-fragments resident in registers: 3 n-frags x 16 k x 2 ----
    // n-frag j covers local rows [warp*24 + j*8, +8); B reg pair (k,k+1)@(n)
    uint32_t bfr[3][16][2];
    {
        const int g4  = lane >> 2;              // n within frag
        const int tig = lane & 3;
#pragma unroll
        for (int j = 0; j < 3; j++) {
            const int n  = warp * 24 + j * 8 + g4;    // local row 0..191
            const int gg = n >> 6, uu = n & 63;
            const float* wrow = W_hh + (size_t)(gg * 256 + crank * 64 + uu) * HH;
#pragma unroll
            for (int s = 0; s < 16; s++) {
                float2 f0 = __ldg((const float2*)(wrow + s * 16 + tig * 2));
                float2 f1 = __ldg((const float2*)(wrow + s * 16 + tig * 2 + 8));
                __half2 h0 = __floats2half2_rn(f0.x, f0.y);
                __half2 h1 = __floats2half2_rn(f1.x, f1.y);
                bfr[j][s][0] = *(uint32_t*)&h0;
                bfr[j][s][1] = *(uint32_t*)&h1;
            }
        }
    }

    const float bias_r = __ldg(b_hh + 0 * 256 + crank * 64 + u);
    const float bias_z = __ldg(b_hh + 1 * 256 + crank * 64 + u);
    const float bias_n = __ldg(b_hh + 2 * 256 + crank * 64 + u);

    const int batch = cid * 4 + kq;
    const float a = fabsf(__ldg(alpha));

    const float* rp = rel_pos + (size_t)batch * SS;
    const float* xg_base = g_xg + ((size_t)batch * SS) * G3 + crank * 64 + u;
    float* hs_base = g_hs + ((size_t)batch * SS) * HH + crank * 64 + u;

    // own slot (local STS) + 3 remote targets (st.async) — unchanged
    float* lown = &hbuf[kq * HBS + crank * HQ + u];
    uint32_t rhb[3], rmb[3];
    {
        uint32_t lslot = smem_u32(lown);
        uint32_t lmbar = smem_u32(&s_mbar[0]);
        int idx = 0;
#pragma unroll
        for (int r = 0; r < 4; r++) {
            if (r != crank) {
                MAPA_U32(rhb[idx], lslot, r);
                MAPA_U32(rmb[idx], lmbar, r);
                idx++;
            }
        }
    }
    const uint32_t lmb = smem_u32(&s_mbar[0]);

    // ldmatrix lane address (row = lane&15, k-half by lane>=16)
    const uint32_t a_lane_base = smem_u32(a_sm) +
        (uint32_t)((lane & 15) * APITCH) + ((lane >= 16) ? 16u : 0u);

    // cvt-stage indices (thread -> (batch, 4 units))
    const int cb = tid >> 6;                    // 0..3
    const int cg0 = (tid & 63) * 4;             // unit group 0..252
    char* a_dst = (char*)a_sm + cb * APITCH + cg0 * 2;
    const int cvt_off = cb * HBS + (cg0 >> 6) * HQ + (cg0 & 63);

    // prefetch t = 0
    float rpt = __ldg(rp);
    float xr = __ldg(xg_base), xz = __ldg(xg_base + 256), xn = __ldg(xg_base + 512);
    float dec = __expf(-a * rpt);

    float h = 0.0f;

    for (int t = 0; t < SS; t++) {
        const uint32_t ph    = (uint32_t)(t & 1);
        const int      poff  = (int)ph * (4 * HBS);
        const uint32_t poffB = ph * (uint32_t)(4 * HBS * 4);
        const uint32_t wp    = (uint32_t)((t >> 1) & 1);

        // decay + local STS + remote async broadcast (fp32, unchanged)
        float hd = h * dec;
        lown[poff] = hd;
        if (tid == 0) MBAR_EXPECT_TX(lmb + ph * 8, 3072u);
        else          MBAR_ARRIVE(lmb + ph * 8);
        ST_ASYNC_F32(rhb[0] + poffB, hd, rmb[0] + ph * 8);
        ST_ASYNC_F32(rhb[1] + poffB, hd, rmb[1] + ph * 8);
        ST_ASYNC_F32(rhb[2] + poffB, hd, rmb[2] + ph * 8);

        // prefetch next xg / rel_pos / decay while exchange is in flight
        const int tn = (t + 1 < SS) ? (t + 1) : (SS - 1);
        const float* xgn = xg_base + (size_t)tn * G3;
        float xr_n = __ldg(xgn), xz_n = __ldg(xgn + 256), xn_n = __ldg(xgn + 512);
        float rpt_n = __ldg(rp + tn);
        float dec_n = __expf(-a * (rpt_n - rpt));

        MBAR_WAIT_CL(lmb + ph * 8, wp);

        // convert hbuf (fp32) -> A-smem rows 0-3 (fp16)
        {
            float4 hv = *(const float4*)(hbuf + poff + cvt_off);
            __half2 p0 = __floats2half2_rn(hv.x, hv.y);
            __half2 p1 = __floats2half2_rn(hv.z, hv.w);
            *(__half2*)a_dst = p0;
            *(__half2*)(a_dst + 4) = p1;
        }
        __syncthreads();

        // tensor matvec: hg[4 x 192] = h[4 x 256] * W^T
        float d0[4] = {0.f, 0.f, 0.f, 0.f};
        float d1[4] = {0.f, 0.f, 0.f, 0.f};
        float d2[4] = {0.f, 0.f, 0.f, 0.f};
#pragma unroll
        for (int s = 0; s < 16; s++) {
            uint32_t afr[4];
            LDSM_X4(afr, a_lane_base + (uint32_t)(s * 32));
            MMA_16816_F16(d0, afr, bfr[0][s][0], bfr[0][s][1]);
            MMA_16816_F16(d1, afr, bfr[1][s][0], bfr[1][s][1]);
            MMA_16816_F16(d2, afr, bfr[2][s][0], bfr[2][s][1]);
        }
        // rows 0-3 (batches) live in lanes 0-15, regs {0,1}
        if (lane < 16) {
            const int bb = lane >> 2;
            const int cc = (lane & 3) * 2;
            float* hgb = hg_sm + bb * 200 + warp * 24 + cc;
            *(float2*)(hgb)      = make_float2(d0[0], d0[1]);
            *(float2*)(hgb + 8)  = make_float2(d1[0], d1[1]);
            *(float2*)(hgb + 16) = make_float2(d2[0], d2[1]);
        }
        __syncthreads();

        const float hr  = hg_sm[kq * 200 + u];
        const float hz  = hg_sm[kq * 200 + 64 + u];
        const float hnv = hg_sm[kq * 200 + 128 + u];

        float r = fast_sig(xr + hr + bias_r);
        float z = fast_sig(xz + hz + bias_z);
        float n = fast_tanh(xn + (hnv + bias_n) * r);
        h = n + z * (hd - n);

        hs_base[(size_t)t * HH] = h;

        xr = xr_n; xz = xz_n; xn = xn_n; rpt = rpt_n; dec = dec_n;
    }

    // no CTA may exit while peers might still st.async into its smem
    cluster.sync();
}

// ===========================================================================
// Kernel 3: out = hs @ W_fc^T + b_fc.
// ===========================================================================
__global__ __launch_bounds__(256) void fc_kernel(
    const float* __restrict__ W_fc, const float* __restrict__ b_fc,
    float* __restrict__ out)
{
    __shared__ float Wsm[OO * HH];
    __shared__ float bsm[OO];
    const int tid = threadIdx.x;
    for (int i = tid; i < OO * HH; i += 256) Wsm[i] = W_fc[i];
    if (tid < OO) bsm[tid] = b_fc[tid];
    __syncthreads();

    const int warp = tid >> 5, lane = tid & 31;
    const size_t m = (size_t)blockIdx.x * 8 + warp;

    const float4* hp = (const float4*)(g_hs + m * HH + lane * 8);
    float4 hv0 = hp[0], hv1 = hp[1];

    float acc[OO];
#pragma unroll
    for (int o = 0; o < OO; o++) {
        const float* w = Wsm + o * HH + lane * 8;
        float4 w0 = *(const float4*)w;
        float4 w1 = *(const float4*)(w + 4);
        float s;
        s = hv0.x * w0.x;
        s = fmaf(hv0.y, w0.y, s);
        s = fmaf(hv0.z, w0.z, s);
        s = fmaf(hv0.w, w0.w, s);
        s = fmaf(hv1.x, w1.x, s);
        s = fmaf(hv1.y, w1.y, s);
        s = fmaf(hv1.z, w1.z, s);
        s = fmaf(hv1.w, w1.w, s);
        acc[o] = s;
    }
#pragma unroll
    for (int sft = 16; sft; sft >>= 1)
#pragma unroll
        for (int o = 0; o < OO; o++)
            acc[o] += __shfl_xor_sync(0xFFFFFFFFu, acc[o], sft);

    if (lane == 0) {
#pragma unroll
        for (int o = 0; o < OO; o++)
            out[m * OO + o] = acc[o] + bsm[o];
    }
}

// ===========================================================================
// Launch
// ===========================================================================
extern "C" void kernel_launch(void* const* d_in, const int* in_sizes, int n_in,
                              void* d_out, int out_size)
{
    const float* x       = (const float*)d_in[0];
    const float* rel_pos = (const float*)d_in[1];
    const float* alpha   = (const float*)d_in[2];
    const float* W_ih    = (const float*)d_in[3];
    const float* b_ih    = (const float*)d_in[4];
    const float* W_hh    = (const float*)d_in[5];
    const float* b_hh    = (const float*)d_in[6];
    const float* W_fc    = (const float*)d_in[7];
    const float* b_fc    = (const float*)d_in[8];
    float* out = (float*)d_out;

    (void)in_sizes; (void)n_in; (void)out_size;

    // 0) fp16 casts
    convert_x_kernel<<<MM, 192>>>(x);
    convert_w_kernel<<<G3, 192>>>(W_ih);

    // 1) Input projection via mma.sync fp16, K=768
    cudaFuncSetAttribute(gemm_mma_kernel,
                         cudaFuncAttributeMaxDynamicSharedMemorySize,
                         NSTG * STG_BYTES);
    dim3 ggrid(6, 1024);
    gemm_mma_kernel<<<ggrid, 256, NSTG * STG_BYTES>>>(b_ih);

    // 2) Scan (4-CTA clusters, tensor-core matvec, st.async exchange)
    scan_kernel<<<128, 256>>>(rel_pos, alpha, W_hh, b_hh);

    // 3) Output FC
    fc_kernel<<<MM / 8, 256>>>(W_fc, b_fc, out);
}

// round 17
// speedup vs baseline: 2.2367x; 1.2170x over previous
#include <cuda_runtime.h>
#include <cuda_bf16.h>
#include <cuda_fp16.h>
#include <cooperative_groups.h>
#include <cstdint>

namespace cg = cooperative_groups;

// Problem constants
#define BB 128          // batch
#define SS 1024         // seq
#define II 768          // input dim
#define HH 256          // hidden
#define OO 6            // output
#define MM (BB * SS)    // 131072 rows
#define G3 (3 * HH)     // 768 gate rows

#define KH   768        // K (pure fp16, no split)
#define KHB  (KH * 2)   // 1536 bytes per row
#define NCHUNK (KH / 64)    // 12
#define NSTG 3
#define STG_BYTES 32768     // A 16KB + B 16KB

typedef unsigned long long ull;

// ---------------------------------------------------------------------------
// Scratch (device globals — allocation-free rule)
// ---------------------------------------------------------------------------
__device__ __align__(128) float g_xg[(size_t)MM * G3];        // [M, 768]
__device__ __align__(128) float g_hs[(size_t)MM * HH];        // [M, 256]
__device__ __align__(128) __half g_ax[(size_t)MM * KH];       // fp16(x)
__device__ __align__(128) __half g_bx[(size_t)G3 * KH];       // fp16(W_ih)

// ---------------------------------------------------------------------------
// Generic-PTX helpers
// ---------------------------------------------------------------------------
__device__ __forceinline__ uint32_t smem_u32(const void* p) {
    uint32_t r;
    asm("{ .reg .u64 t; cvta.to.shared.u64 t, %1; cvt.u32.u64 %0, t; }"
        : "=r"(r) : "l"(p));
    return r;
}

__device__ __forceinline__ void cpa16(uint32_t saddr, const char* g) {
    asm volatile("cp.async.cg.shared.global [%0], [%1], 16;" :: "r"(saddr), "l"(g));
}

#define LDSM_X4(r, addr) \
    asm volatile("ldmatrix.sync.aligned.m8n8.x4.shared.b16 {%0,%1,%2,%3}, [%4];" \
                 : "=r"((r)[0]), "=r"((r)[1]), "=r"((r)[2]), "=r"((r)[3]) : "r"(addr))

#define MMA_16816_F16(d, a, b0, b1) \
    asm volatile("mma.sync.aligned.m16n8k16.row.col.f32.f16.f16.f32 " \
                 "{%0,%1,%2,%3}, {%4,%5,%6,%7}, {%8,%9}, {%0,%1,%2,%3};" \
                 : "+f"((d)[0]), "+f"((d)[1]), "+f"((d)[2]), "+f"((d)[3]) \
                 : "r"((a)[0]), "r"((a)[1]), "r"((a)[2]), "r"((a)[3]), \
                   "r"(b0), "r"(b1))

#define MBAR_INIT(addr, cnt) \
    asm volatile("mbarrier.init.shared.b64 [%0], %1;" :: "r"(addr), "r"(cnt) : "memory")

#define MBAR_EXPECT_TX(addr, tx) \
    asm volatile("mbarrier.arrive.expect_tx.shared.b64 _, [%0], %1;" \
                 :: "r"(addr), "r"(tx) : "memory")

#define MBAR_ARRIVE(addr) \
    asm volatile("mbarrier.arrive.shared.b64 _, [%0];" :: "r"(addr) : "memory")

#define MBAR_WAIT_CL(addr, parity) do {                                        \
    uint32_t _m = (addr); uint32_t _p = (parity); uint32_t _d;                 \
    asm volatile("{\n\t.reg .pred p;\n\t"                                      \
        "mbarrier.try_wait.parity.acquire.cluster.shared::cta.b64 p, [%1], %2;\n\t" \
        "selp.b32 %0, 1, 0, p;\n\t}"                                           \
        : "=r"(_d) : "r"(_m), "r"(_p) : "memory");                             \
    if (!_d) {                                                                 \
        asm volatile("{\n\t.reg .pred P1;\n\t"                                 \
            "W_%=:\n\t"                                                        \
            "mbarrier.try_wait.parity.acquire.cluster.shared::cta.b64 P1, [%0], %1, 0x989680;\n\t" \
            "@P1 bra.uni D_%=;\n\t"                                            \
            "bra.uni W_%=;\n\t"                                                \
            "D_%=:\n\t}" :: "r"(_m), "r"(_p) : "memory");                      \
    }                                                                          \
} while (0)

#define ST_ASYNC_U32(raddr, v, rmbar) \
    asm volatile("st.async.shared::cluster.mbarrier::complete_tx::bytes.b32 [%0], %1, [%2];" \
                 :: "r"(raddr), "r"(v), "r"(rmbar) : "memory")

#define MAPA_U32(out, local, rank) \
    asm("mapa.shared::cluster.u32 %0, %1, %2;" : "=r"(out) : "r"(local), "r"(rank))

// ===========================================================================
// Convert kernels: straight fp16 casts (no split).
// ===========================================================================
__global__ __launch_bounds__(192) void convert_x_kernel(const float* __restrict__ x)
{
    const size_t row = blockIdx.x;
    const int t = threadIdx.x;
    float4 v = __ldg((const float4*)(x + row * II) + t);
    __half2 hp0 = __halves2half2(__float2half_rn(v.x), __float2half_rn(v.y));
    __half2 hp1 = __halves2half2(__float2half_rn(v.z), __float2half_rn(v.w));
    __half2* base = (__half2*)(g_ax + row * KH);
    base[t * 2]     = hp0;
    base[t * 2 + 1] = hp1;
}

__global__ __launch_bounds__(192) void convert_w_kernel(const float* __restrict__ W)
{
    const size_t row = blockIdx.x;
    const int t = threadIdx.x;
    float4 v = __ldg((const float4*)(W + row * II) + t);
    __half2 hp0 = __halves2half2(__float2half_rn(v.x), __float2half_rn(v.y));
    __half2 hp1 = __halves2half2(__float2half_rn(v.z), __float2half_rn(v.w));
    __half2* base = (__half2*)(g_bx + row * KH);
    base[t * 2]     = hp0;
    base[t * 2 + 1] = hp1;
}

// ===========================================================================
// Kernel 1: xg = x @ W_ih^T + b_ih via mma.sync fp16 (f32 accum), K=768.
// (exact R15/R16 — known good)
// ===========================================================================
__global__ __launch_bounds__(256, 2) void gemm_mma_kernel(
    const float* __restrict__ bias)
{
    extern __shared__ __align__(1024) char dsm[];
    __shared__ float s_bias[128];

    const int tid  = threadIdx.x;
    const int lane = tid & 31;
    const int warp = tid >> 5;
    const int wm = warp >> 2;
    const int wn = warp & 3;
    const int n0 = blockIdx.x * 128;
    const size_t m0 = (size_t)blockIdx.y * 128;

    const uint32_t smem_base = smem_u32(dsm);

    if (tid < 128) s_bias[tid] = __ldg(bias + n0 + tid);

    const char* gA = (const char*)(g_ax) + m0 * KHB;
    const char* gB = (const char*)(g_bx) + (size_t)n0 * KHB;

    auto issue_loads = [&](int slot, int kbyte) {
        const uint32_t stgA = smem_base + slot * STG_BYTES;
        const uint32_t stgB = stgA + 16384;
#pragma unroll
        for (int i = 0; i < 4; i++) {
            int seg = tid + i * 256;
            int r = seg >> 3, c = seg & 7;
            uint32_t off = (uint32_t)(r * 128 + ((c ^ (r & 7)) << 4));
            const size_t goff = (size_t)r * KHB + kbyte + c * 16;
            cpa16(stgA + off, gA + goff);
            cpa16(stgB + off, gB + goff);
        }
    };

    const int lrow = (lane & 7) + ((lane >> 3) & 1) * 8;
    const int cp   = lane >> 4;
    const int arow = wm * 64 + lrow;
    const int brow = wn * 32 + lrow;

    float acc[4][4][4];
#pragma unroll
    for (int f = 0; f < 4; f++)
#pragma unroll
        for (int g = 0; g < 4; g++)
#pragma unroll
            for (int r = 0; r < 4; r++) acc[f][g][r] = 0.0f;

    issue_loads(0, 0);
    asm volatile("cp.async.commit_group;" ::: "memory");
    issue_loads(1, 128);
    asm volatile("cp.async.commit_group;" ::: "memory");

    for (int c = 0; c < NCHUNK; c++) {
        asm volatile("cp.async.wait_group 1;" ::: "memory");
        __syncthreads();

        const int lc = c + 2;
        if (lc < NCHUNK) issue_loads(lc % NSTG, lc * 128);
        asm volatile("cp.async.commit_group;" ::: "memory");

        const uint32_t stgA = smem_base + (c % NSTG) * STG_BYTES;
        const uint32_t stgB = stgA + 16384;

#pragma unroll
        for (int s = 0; s < 4; s++) {
            const int ach = ((2 * s + cp) ^ (arow & 7)) << 4;
            const int bch = ((2 * s + cp) ^ (brow & 7)) << 4;
            uint32_t a[4][4];
            uint32_t b[2][4];
#pragma unroll
            for (int f = 0; f < 4; f++)
                LDSM_X4(a[f], stgA + (uint32_t)((arow + f * 16) * 128 + ach));
#pragma unroll
            for (int g2 = 0; g2 < 2; g2++)
                LDSM_X4(b[g2], stgB + (uint32_t)((brow + g2 * 16) * 128 + bch));
#pragma unroll
            for (int f = 0; f < 4; f++) {
#pragma unroll
                for (int g = 0; g < 4; g++)
                    MMA_16816_F16(acc[f][g], a[f], b[g >> 1][g & 1], b[g >> 1][(g & 1) + 2]);
            }
        }
    }

    const int qrow = lane >> 2;
    const int qcol = (lane & 3) * 2;
#pragma unroll
    for (int f = 0; f < 4; f++) {
        const size_t gr = m0 + wm * 64 + f * 16 + qrow;
#pragma unroll
        for (int g = 0; g < 4; g++) {
            const int lc = wn * 32 + g * 8 + qcol;
            const float b0 = s_bias[lc], b1 = s_bias[lc + 1];
            float* p0 = g_xg + gr * G3 + n0 + lc;
            float* p1 = p0 + 8 * G3;
            *(float2*)p0 = make_float2(acc[f][g][0] + b0, acc[f][g][1] + b1);
            *(float2*)p1 = make_float2(acc[f][g][2] + b0, acc[f][g][3] + b1);
        }
    }
}

// ===========================================================================
// Kernel 2: GRU scan — tensor-core matvec, fragment-aligned ownership.
// 4-CTA cluster = 4 batches; CTA rank owns units [crank*64, +64).
// B frag (warp w, j) = gate j, local units w*8 + (lane>>2): D lanes 0-15
// hold all 3 gates for (batch = lane>>2, units w*8+(lane&3)*2, +1).
// Exchange: owning lane packs half2(hd0,hd1), st.asyncs 4B to all 4 ranks
// directly into A-smem[parity][row=batch][col=global unit]. No cvt stage,
// no hg smem, no __syncthreads in the loop.
// ===========================================================================
#define APITCH 528                       // A row pitch (bytes)
#define ABUF_BYTES (16 * APITCH)         // 8448 per parity buffer
#define ABUF_HALFS (16 * (APITCH / 2))

__device__ __forceinline__ float fast_sig(float x) {
    return __fdividef(1.f, 1.f + __expf(-x));
}
__device__ __forceinline__ float fast_tanh(float x) {
    return 1.f - __fdividef(2.f, __expf(2.f * x) + 1.f);
}

__global__ void __cluster_dims__(4, 1, 1) __launch_bounds__(256, 1)
scan_kernel(const float* __restrict__ rel_pos, const float* __restrict__ alpha,
            const float* __restrict__ W_hh, const float* __restrict__ b_hh)
{
    __shared__ __align__(16) __half a_sm[2 * ABUF_HALFS];   // 16.9 KB
    __shared__ __align__(8) unsigned long long s_mbar[2];

    cg::cluster_group cluster = cg::this_cluster();
    const int crank = cluster.block_rank();     // 0..3
    const int cid   = blockIdx.x >> 2;          // 0..31
    const int tid   = threadIdx.x;
    const int lane  = tid & 31;
    const int warp  = tid >> 5;                 // 0..7
    const bool act  = (lane < 16);
    const int b     = (lane >> 2) & 3;          // batch (active lanes)
    const int u0    = warp * 8 + (lane & 3) * 2;  // local unit (even)
    const int gu    = crank * 64 + u0;            // global unit

    if (tid == 0) {
        MBAR_INIT(smem_u32(&s_mbar[0]), 256);
        MBAR_INIT(smem_u32(&s_mbar[1]), 256);
        asm volatile("fence.mbarrier_init.release.cluster;" ::: "memory");
    }
    for (int i = tid; i < 2 * ABUF_HALFS; i += 256)
        a_sm[i] = __ushort_as_half((unsigned short)0);
    cluster.sync();

    // ---- W_hh B-fragments: frag j = gate j, rows = j*64 + warp*8 + (lane>>2)
    uint32_t bfr[3][16][2];
    {
        const int r4  = lane >> 2;
        const int tig = lane & 3;
#pragma unroll
        for (int j = 0; j < 3; j++) {
            const float* wrow = W_hh +
                (size_t)(j * 256 + crank * 64 + warp * 8 + r4) * HH;
#pragma unroll
            for (int s = 0; s < 16; s++) {
                float2 f0 = __ldg((const float2*)(wrow + s * 16 + tig * 2));
                float2 f1 = __ldg((const float2*)(wrow + s * 16 + tig * 2 + 8));
                __half2 h0 = __floats2half2_rn(f0.x, f0.y);
                __half2 h1 = __floats2half2_rn(f1.x, f1.y);
                bfr[j][s][0] = *(uint32_t*)&h0;
                bfr[j][s][1] = *(uint32_t*)&h1;
            }
        }
    }

    // biases for the 2 owned units
    const float2 br2 = __ldg((const float2*)(b_hh + 0 * 256 + gu));
    const float2 bz2 = __ldg((const float2*)(b_hh + 1 * 256 + gu));
    const float2 bn2 = __ldg((const float2*)(b_hh + 2 * 256 + gu));

    const int batch = cid * 4 + b;
    const float a = fabsf(__ldg(alpha));
    const float* rp = rel_pos + (size_t)batch * SS;
    const float* xgb = g_xg + ((size_t)batch * SS) * G3 + gu;
    float* hsb = g_hs + ((size_t)batch * SS) * HH + gu;

    // exchange targets: a_sm row b, col gu (4 bytes), all 4 ranks
    uint32_t rdst[4], rmb[4];
    {
        uint32_t lslot = smem_u32((const char*)a_sm + b * APITCH + gu * 2);
        uint32_t lmbar = smem_u32(&s_mbar[0]);
#pragma unroll
        for (int r = 0; r < 4; r++) {
            MAPA_U32(rdst[r], lslot, r);
            MAPA_U32(rmb[r], lmbar, r);
        }
    }
    const uint32_t lmb = smem_u32(&s_mbar[0]);
    const uint32_t abase = smem_u32(a_sm) +
        (uint32_t)((lane & 15) * APITCH) + ((lane >= 16) ? 16u : 0u);

    // prefetch t = 0
    float rpt = __ldg(rp);
    float2 xr2 = __ldg((const float2*)(xgb));
    float2 xz2 = __ldg((const float2*)(xgb + 256));
    float2 xn2 = __ldg((const float2*)(xgb + 512));
    float dec = __expf(-a * rpt);

    float h0 = 0.0f, h1 = 0.0f;

    for (int t = 0; t < SS; t++) {
        const uint32_t ph    = (uint32_t)(t & 1);
        const uint32_t pboff = ph * (uint32_t)ABUF_BYTES;
        const uint32_t wp    = (uint32_t)((t >> 1) & 1);

        // decay + exchange (half2 straight into A operand)
        const float hd0 = h0 * dec, hd1 = h1 * dec;
        if (tid == 0) MBAR_EXPECT_TX(lmb + ph * 8, 2048u);
        else          MBAR_ARRIVE(lmb + ph * 8);
        if (act) {
            __half2 hp = __floats2half2_rn(hd0, hd1);
            const uint32_t v = *(uint32_t*)&hp;
            ST_ASYNC_U32(rdst[0] + pboff, v, rmb[0] + ph * 8);
            ST_ASYNC_U32(rdst[1] + pboff, v, rmb[1] + ph * 8);
            ST_ASYNC_U32(rdst[2] + pboff, v, rmb[2] + ph * 8);
            ST_ASYNC_U32(rdst[3] + pboff, v, rmb[3] + ph * 8);
        }

        // prefetch next xg / rel_pos / decay while exchange is in flight
        const int tn = (t + 1 < SS) ? (t + 1) : (SS - 1);
        const float* xgn = xgb + (size_t)tn * G3;
        float2 nr = __ldg((const float2*)(xgn));
        float2 nz = __ldg((const float2*)(xgn + 256));
        float2 nn = __ldg((const float2*)(xgn + 512));
        float rptn = __ldg(rp + tn);
        float decn = __expf(-a * (rptn - rpt));

        MBAR_WAIT_CL(lmb + ph * 8, wp);

        // tensor matvec with k-split accumulators
        float dA0[4] = {0,0,0,0}, dA1[4] = {0,0,0,0}, dA2[4] = {0,0,0,0};
        float dB0[4] = {0,0,0,0}, dB1[4] = {0,0,0,0}, dB2[4] = {0,0,0,0};
#pragma unroll
        for (int s = 0; s < 8; s++) {
            uint32_t afr[4];
            LDSM_X4(afr, abase + pboff + (uint32_t)(s * 32));
            MMA_16816_F16(dA0, afr, bfr[0][s][0], bfr[0][s][1]);
            MMA_16816_F16(dA1, afr, bfr[1][s][0], bfr[1][s][1]);
            MMA_16816_F16(dA2, afr, bfr[2][s][0], bfr[2][s][1]);
        }
#pragma unroll
        for (int s = 8; s < 16; s++) {
            uint32_t afr[4];
            LDSM_X4(afr, abase + pboff + (uint32_t)(s * 32));
            MMA_16816_F16(dB0, afr, bfr[0][s][0], bfr[0][s][1]);
            MMA_16816_F16(dB1, afr, bfr[1][s][0], bfr[1][s][1]);
            MMA_16816_F16(dB2, afr, bfr[2][s][0], bfr[2][s][1]);
        }

        if (act) {
            const float hr0 = dA0[0] + dB0[0], hr1 = dA0[1] + dB0[1];
            const float hz0 = dA1[0] + dB1[0], hz1 = dA1[1] + dB1[1];
            const float hn0 = dA2[0] + dB2[0], hn1 = dA2[1] + dB2[1];

            float r0 = fast_sig(xr2.x + hr0 + br2.x);
            float z0 = fast_sig(xz2.x + hz0 + bz2.x);
            float n0 = fast_tanh(xn2.x + (hn0 + bn2.x) * r0);
            h0 = n0 + z0 * (hd0 - n0);

            float r1 = fast_sig(xr2.y + hr1 + br2.y);
            float z1 = fast_sig(xz2.y + hz1 + bz2.y);
            float n1 = fast_tanh(xn2.y + (hn1 + bn2.y) * r1);
            h1 = n1 + z1 * (hd1 - n1);

            *(float2*)(hsb + (size_t)t * HH) = make_float2(h0, h1);
        }

        xr2 = nr; xz2 = nz; xn2 = nn; rpt = rptn; dec = decn;
    }

    // no CTA may exit while peers might still st.async into its smem
    cluster.sync();
}

// ===========================================================================
// Kernel 3: out = hs @ W_fc^T + b_fc.
// ===========================================================================
__global__ __launch_bounds__(256) void fc_kernel(
    const float* __restrict__ W_fc, const float* __restrict__ b_fc,
    float* __restrict__ out)
{
    __shared__ float Wsm[OO * HH];
    __shared__ float bsm[OO];
    const int tid = threadIdx.x;
    for (int i = tid; i < OO * HH; i += 256) Wsm[i] = W_fc[i];
    if (tid < OO) bsm[tid] = b_fc[tid];
    __syncthreads();

    const int warp = tid >> 5, lane = tid & 31;
    const size_t m = (size_t)blockIdx.x * 8 + warp;

    const float4* hp = (const float4*)(g_hs + m * HH + lane * 8);
    float4 hv0 = hp[0], hv1 = hp[1];

    float acc[OO];
#pragma unroll
    for (int o = 0; o < OO; o++) {
        const float* w = Wsm + o * HH + lane * 8;
        float4 w0 = *(const float4*)w;
        float4 w1 = *(const float4*)(w + 4);
        float s;
        s = hv0.x * w0.x;
        s = fmaf(hv0.y, w0.y, s);
        s = fmaf(hv0.z, w0.z, s);
        s = fmaf(hv0.w, w0.w, s);
        s = fmaf(hv1.x, w1.x, s);
        s = fmaf(hv1.y, w1.y, s);
        s = fmaf(hv1.z, w1.z, s);
        s = fmaf(hv1.w, w1.w, s);
        acc[o] = s;
    }
#pragma unroll
    for (int sft = 16; sft; sft >>= 1)
#pragma unroll
        for (int o = 0; o < OO; o++)
            acc[o] += __shfl_xor_sync(0xFFFFFFFFu, acc[o], sft);

    if (lane == 0) {
#pragma unroll
        for (int o = 0; o < OO; o++)
            out[m * OO + o] = acc[o] + bsm[o];
    }
}

// ===========================================================================
// Launch
// ===========================================================================
extern "C" void kernel_launch(void* const* d_in, const int* in_sizes, int n_in,
                              void* d_out, int out_size)
{
    const float* x       = (const float*)d_in[0];
    const float* rel_pos = (const float*)d_in[1];
    const float* alpha   = (const float*)d_in[2];
    const float* W_ih    = (const float*)d_in[3];
    const float* b_ih    = (const float*)d_in[4];
    const float* W_hh    = (const float*)d_in[5];
    const float* b_hh    = (const float*)d_in[6];
    const float* W_fc    = (const float*)d_in[7];
    const float* b_fc    = (const float*)d_in[8];
    float* out = (float*)d_out;

    (void)in_sizes; (void)n_in; (void)out_size;

    // 0) fp16 casts
    convert_x_kernel<<<MM, 192>>>(x);
    convert_w_kernel<<<G3, 192>>>(W_ih);

    // 1) Input projection via mma.sync fp16, K=768
    cudaFuncSetAttribute(gemm_mma_kernel,
                         cudaFuncAttributeMaxDynamicSharedMemorySize,
                         NSTG * STG_BYTES);
    dim3 ggrid(6, 1024);
    gemm_mma_kernel<<<ggrid, 256, NSTG * STG_BYTES>>>(b_ih);

    // 2) Scan (4-CTA clusters, fragment-aligned tensor matvec)
    scan_kernel<<<128, 256>>>(rel_pos, alpha, W_hh, b_hh);

    // 3) Output FC
    fc_kernel<<<MM / 8, 256>>>(W_fc, b_fc, out);
}